// round 6
// baseline (speedup 1.0000x reference)
#include <cuda_runtime.h>
#include <cuda_bf16.h>
#include <mma.h>
#include <math.h>
#include <stdint.h>

using namespace nvcuda;

// Problem constants
#define NN 100000
#define DD 128
#define EE 500000
#define RR 3

// ---------------------------------------------------------------------------
// Static device scratch (allocation-free rule). Per-relation buffers reused
// across the sequential relation chain (keeps L2 working set ~102 MB).
// ---------------------------------------------------------------------------
__device__ float g_feat[(size_t)NN * DD];   // 51.2 MB (one relation at a time)
__device__ float g_el[NN];
__device__ float g_er[NN];
__device__ float g_s[RR * NN];              // expsum per dst (zeroed once)
__device__ float g_w[EE];                   // per-edge exp(e) cache (reused per rel)

union Pack8 { __nv_bfloat16 h[8]; uint4 u; };

// ---------------------------------------------------------------------------
// GEMM: feat = x @ W[r]^T via bf16x3 split wmma (m16n16k16).
// CTA tile 128x128, K in 4 chunks of 32. 512 threads = 16 warps (4x4),
// warp tile 32x32 = 2x2 acc frags. Fused-term inner loop: one set of
// ah/al/bh/bl fragment loads feeds all 3 split-term MMAs (12 MMA / 8 loads).
// A (x) is read fp32 and split hi/lo on the fly (same as W path).
// Epilogue: stage C in smem, write feat + el/er.
// ---------------------------------------------------------------------------
#define KC    32
#define LDT   40          // bf16 tile stride (elems)
#define LDC   132         // C stage stride (floats)
#define TB    (128 * LDT) // elems per tile buffer
#define SM_TOT (128 * LDC * 4)   // 67584 B (>= 4*TB*2 = 40960)

__device__ __forceinline__ void split8(const float* __restrict__ p, Pack8& hi, Pack8& lo)
{
    float4 v0 = __ldg((const float4*)p);
    float4 v1 = __ldg((const float4*)(p + 4));
    float wv[8] = {v0.x, v0.y, v0.z, v0.w, v1.x, v1.y, v1.z, v1.w};
#pragma unroll
    for (int j = 0; j < 8; j++) {
        __nv_bfloat16 h = __float2bfloat16(wv[j]);
        hi.h[j] = h;
        lo.h[j] = __float2bfloat16(wv[j] - __bfloat162float(h));
    }
}

__global__ void __launch_bounds__(512) gemm_feat_kernel(
    const float* __restrict__ x, const float* __restrict__ Wr,
    const float* __restrict__ al_p, const float* __restrict__ ar_p)
{
    extern __shared__ char smraw[];
    __nv_bfloat16* smA_hi = (__nv_bfloat16*)smraw;
    __nv_bfloat16* smA_lo = smA_hi + TB;
    __nv_bfloat16* smB_hi = smA_lo + TB;
    __nv_bfloat16* smB_lo = smB_hi + TB;
    float*         smC    = (float*)smraw;

    const int tid  = threadIdx.x;
    const int wid  = tid >> 5;
    const int lane = tid & 31;
    const int row0 = blockIdx.x * 128;
    const int wm   = wid >> 2;      // 0..3 : 32-row slab
    const int wn   = wid & 3;       // 0..3 : 32-col slab

    wmma::fragment<wmma::accumulator, 16, 16, 16, float> acc[2][2];
#pragma unroll
    for (int mi = 0; mi < 2; mi++)
#pragma unroll
        for (int ni = 0; ni < 2; ni++) wmma::fill_fragment(acc[mi][ni], 0.0f);

    for (int c = 0; c < 4; c++) {
        // A chunk: x rows, fp32 -> bf16 hi/lo on the fly. 512 thr x 8 elems.
        {
            int row  = tid >> 2;
            int k8   = (tid & 3) << 3;
            int grow = row0 + row;
            Pack8 hi, lo;
            if (grow < NN) {
                split8(x + (size_t)grow * DD + c * KC + k8, hi, lo);
            } else {
                hi.u = make_uint4(0u, 0u, 0u, 0u); lo.u = hi.u;
            }
            *(uint4*)(smA_hi + row * LDT + k8) = hi.u;
            *(uint4*)(smA_lo + row * LDT + k8) = lo.u;
        }
        // B chunk: W[n][k] fp32 -> bf16 hi/lo.
        {
            int n  = tid >> 2;
            int k8 = (tid & 3) << 3;
            Pack8 hi, lo;
            split8(Wr + (size_t)n * DD + c * KC + k8, hi, lo);
            *(uint4*)(smB_hi + n * LDT + k8) = hi.u;
            *(uint4*)(smB_lo + n * LDT + k8) = lo.u;
        }
        __syncthreads();

        // Fused-term k-loop: 8 fragment loads feed 12 MMAs
#pragma unroll
        for (int kk = 0; kk < KC; kk += 16) {
            wmma::fragment<wmma::matrix_a, 16, 16, 16, __nv_bfloat16, wmma::row_major> ah[2], alx[2];
            wmma::fragment<wmma::matrix_b, 16, 16, 16, __nv_bfloat16, wmma::col_major> bh[2], blx[2];
#pragma unroll
            for (int mi = 0; mi < 2; mi++) {
                wmma::load_matrix_sync(ah[mi],  smA_hi + (wm * 32 + mi * 16) * LDT + kk, LDT);
                wmma::load_matrix_sync(alx[mi], smA_lo + (wm * 32 + mi * 16) * LDT + kk, LDT);
            }
#pragma unroll
            for (int ni = 0; ni < 2; ni++) {
                wmma::load_matrix_sync(bh[ni],  smB_hi + (wn * 32 + ni * 16) * LDT + kk, LDT);
                wmma::load_matrix_sync(blx[ni], smB_lo + (wn * 32 + ni * 16) * LDT + kk, LDT);
            }
#pragma unroll
            for (int mi = 0; mi < 2; mi++)
#pragma unroll
                for (int ni = 0; ni < 2; ni++) {
                    wmma::mma_sync(acc[mi][ni], ah[mi],  bh[ni],  acc[mi][ni]);
                    wmma::mma_sync(acc[mi][ni], alx[mi], bh[ni],  acc[mi][ni]);
                    wmma::mma_sync(acc[mi][ni], ah[mi],  blx[ni], acc[mi][ni]);
                }
        }
        __syncthreads();
    }

    // --- Epilogue: stage C in smem, then feat + el/er ---
#pragma unroll
    for (int mi = 0; mi < 2; mi++)
#pragma unroll
        for (int ni = 0; ni < 2; ni++)
            wmma::store_matrix_sync(smC + (wm * 32 + mi * 16) * LDC + wn * 32 + ni * 16,
                                    acc[mi][ni], LDC, wmma::mem_row_major);
    __syncthreads();

    const int c0 = lane * 4;
    const float al0 = __ldg(al_p + c0), al1 = __ldg(al_p + c0 + 1),
                al2 = __ldg(al_p + c0 + 2), al3 = __ldg(al_p + c0 + 3);
    const float ar0 = __ldg(ar_p + c0), ar1 = __ldg(ar_p + c0 + 1),
                ar2 = __ldg(ar_p + c0 + 2), ar3 = __ldg(ar_p + c0 + 3);

#pragma unroll
    for (int rr = 0; rr < 8; rr++) {
        int row  = wid * 8 + rr;
        int grow = row0 + row;
        float4 v = *(const float4*)(smC + row * LDC + c0);
        float el = v.x * al0 + v.y * al1 + v.z * al2 + v.w * al3;
        float er = v.x * ar0 + v.y * ar1 + v.z * ar2 + v.w * ar3;
#pragma unroll
        for (int off = 16; off > 0; off >>= 1) {
            el += __shfl_xor_sync(0xffffffffu, el, off);
            er += __shfl_xor_sync(0xffffffffu, er, off);
        }
        if (grow < NN) {
            *(float4*)(g_feat + (size_t)grow * DD + c0) = v;
            if (lane == 0) { g_el[grow] = el; g_er[grow] = er; }
        }
    }
}

// ---------------------------------------------------------------------------
// Init kernels
// ---------------------------------------------------------------------------
__global__ void init_s_kernel()
{
    int i = blockIdx.x * blockDim.x + threadIdx.x;
    if (i < RR * NN) g_s[i] = 0.f;
}

__global__ void init_out_kernel(float* __restrict__ out, const float* __restrict__ bias)
{
    int i = blockIdx.x * blockDim.x + threadIdx.x;
    if (i < NN * DD) {
        int d = i & 127;
        out[i] = (bias[d] + bias[DD + d] + bias[2 * DD + d]) * (1.f / 3.f);
    }
}

// ---------------------------------------------------------------------------
// Edge pass 1 (per relation): ex = exp(leakyrelu(el[src]+er[dst])) cached to
// g_w; segment-sum into g_s. (No max pass: |e| bounded small; softmax is
// shift-invariant.)
// ---------------------------------------------------------------------------
__global__ void pass_sum_kernel(const int* __restrict__ src, const int* __restrict__ dst,
                                float* __restrict__ s_rel)
{
    int i = blockIdx.x * blockDim.x + threadIdx.x;
    if (i >= EE) return;
    int sN = src[i], dN = dst[i];
    float e = g_el[sN] + g_er[dN];
    e = e >= 0.f ? e : 0.2f * e;
    float ex = __expf(e);
    g_w[i] = ex;
    atomicAdd(s_rel + dN, ex);
}

// Edge pass 2 (per relation): out[dst] += (w / (s*R)) * feat[src]
// (warp per edge, float4 per lane, red.global.add.v4.f32; feat is L2-hot)
__global__ void __launch_bounds__(256) pass_agg_kernel(
    const int* __restrict__ src, const int* __restrict__ dst,
    const float* __restrict__ s_rel, float* __restrict__ out)
{
    int gw   = (blockIdx.x * blockDim.x + threadIdx.x) >> 5;  // edge id
    int lane = threadIdx.x & 31;
    if (gw >= EE) return;
    int sN = src[gw], dN = dst[gw];                           // broadcast loads
    float w = g_w[gw] / (s_rel[dN] * 3.0f);

    const float4 f = *(const float4*)(g_feat + (size_t)sN * DD + lane * 4);
    float* p = out + (size_t)dN * DD + lane * 4;
    asm volatile("red.global.add.v4.f32 [%0], {%1, %2, %3, %4};"
                 :: "l"(p), "f"(w * f.x), "f"(w * f.y), "f"(w * f.z), "f"(w * f.w)
                 : "memory");
}

// ---------------------------------------------------------------------------
// Launch: relation-sequential chain for L2 residency of feat[r] + out
// ---------------------------------------------------------------------------
extern "C" void kernel_launch(void* const* d_in, const int* in_sizes, int n_in,
                              void* d_out, int out_size)
{
    const float* x    = (const float*)d_in[0];
    const int*   src  = (const int*)  d_in[1];
    const int*   dst  = (const int*)  d_in[2];
    const float* W    = (const float*)d_in[3];
    const float* al   = (const float*)d_in[4];
    const float* ar   = (const float*)d_in[5];
    const float* bias = (const float*)d_in[6];
    float* out = (float*)d_out;

    cudaFuncSetAttribute(gemm_feat_kernel, cudaFuncAttributeMaxDynamicSharedMemorySize, SM_TOT);

    init_out_kernel<<<(NN * DD + 255) / 256, 256>>>(out, bias);
    init_s_kernel<<<(RR * NN + 255) / 256, 256>>>();

    float* g_s_ptr = nullptr;
    cudaGetSymbolAddress((void**)&g_s_ptr, g_s);

    for (int r = 0; r < RR; r++) {
        const int* sr = src + (size_t)r * EE;
        const int* dr = dst + (size_t)r * EE;
        float* s_rel  = g_s_ptr + (size_t)r * NN;

        gemm_feat_kernel<<<(NN + 127) / 128, 512, SM_TOT>>>(
            x, W + (size_t)r * DD * DD, al + (size_t)r * DD, ar + (size_t)r * DD);
        pass_sum_kernel<<<(EE + 255) / 256, 256>>>(sr, dr, s_rel);
        pass_agg_kernel<<<(EE * 32 + 255) / 256, 256>>>(sr, dr, s_rel, out);
    }
}

// round 7
// speedup vs baseline: 1.2488x; 1.2488x over previous
#include <cuda_runtime.h>
#include <cuda_bf16.h>
#include <mma.h>
#include <math.h>
#include <stdint.h>

using namespace nvcuda;

// Problem constants
#define NN 100000
#define DD 128
#define EE 500000
#define RR 3
#define RRNN (RR * NN)                 // 300000
#define NB1  ((RRNN + 1023) / 1024)    // 293 scan blocks

// ---------------------------------------------------------------------------
// Static device scratch (allocation-free rule)
// ---------------------------------------------------------------------------
__device__ float g_feat[(size_t)RR * NN * DD];  // 153.6 MB
__device__ float g_el[RRNN];
__device__ float g_er[RRNN];
__device__ int   g_cnt[RRNN];                   // per-(rel,dst) degree
__device__ int   g_off[RRNN];                   // CSR begin offsets
__device__ int   g_cur[RRNN];                   // fill cursor -> end offsets
__device__ int   g_bsum[NB1];                   // scan block sums
__device__ int   g_csrc[(size_t)RR * EE];       // CSR: src node per slot

union Pack8 { __nv_bfloat16 h[8]; uint4 u; };

// ---------------------------------------------------------------------------
// GEMM: feat[r] = x @ W[r]^T via bf16x3 split wmma (m16n16k16).
// CTA tile 128x128, K in 4 chunks of 32, 512 threads = 16 warps (4x4).
// ---------------------------------------------------------------------------
#define KC    32
#define LDT   40
#define LDC   132
#define TB    (128 * LDT)
#define SM_TOT (128 * LDC * 4)   // 67584 B

__device__ __forceinline__ void split8(const float* __restrict__ p, Pack8& hi, Pack8& lo)
{
    float4 v0 = __ldg((const float4*)p);
    float4 v1 = __ldg((const float4*)(p + 4));
    float wv[8] = {v0.x, v0.y, v0.z, v0.w, v1.x, v1.y, v1.z, v1.w};
#pragma unroll
    for (int j = 0; j < 8; j++) {
        __nv_bfloat16 h = __float2bfloat16(wv[j]);
        hi.h[j] = h;
        lo.h[j] = __float2bfloat16(wv[j] - __bfloat162float(h));
    }
}

__global__ void __launch_bounds__(512) gemm_feat_kernel(
    const float* __restrict__ x, const float* __restrict__ W,
    const float* __restrict__ attn_l, const float* __restrict__ attn_r)
{
    extern __shared__ char smraw[];
    __nv_bfloat16* smA_hi = (__nv_bfloat16*)smraw;
    __nv_bfloat16* smA_lo = smA_hi + TB;
    __nv_bfloat16* smB_hi = smA_lo + TB;
    __nv_bfloat16* smB_lo = smB_hi + TB;
    float*         smC    = (float*)smraw;

    const int tid  = threadIdx.x;
    const int wid  = tid >> 5;
    const int lane = tid & 31;
    const int rel  = blockIdx.y;
    const int row0 = blockIdx.x * 128;
    const int wm   = wid >> 2;
    const int wn   = wid & 3;

    const float* Wr = W + (size_t)rel * DD * DD;

    wmma::fragment<wmma::accumulator, 16, 16, 16, float> acc[2][2];
#pragma unroll
    for (int mi = 0; mi < 2; mi++)
#pragma unroll
        for (int ni = 0; ni < 2; ni++) wmma::fill_fragment(acc[mi][ni], 0.0f);

    for (int c = 0; c < 4; c++) {
        {
            int row  = tid >> 2;
            int k8   = (tid & 3) << 3;
            int grow = row0 + row;
            Pack8 hi, lo;
            if (grow < NN) {
                split8(x + (size_t)grow * DD + c * KC + k8, hi, lo);
            } else {
                hi.u = make_uint4(0u, 0u, 0u, 0u); lo.u = hi.u;
            }
            *(uint4*)(smA_hi + row * LDT + k8) = hi.u;
            *(uint4*)(smA_lo + row * LDT + k8) = lo.u;
        }
        {
            int n  = tid >> 2;
            int k8 = (tid & 3) << 3;
            Pack8 hi, lo;
            split8(Wr + (size_t)n * DD + c * KC + k8, hi, lo);
            *(uint4*)(smB_hi + n * LDT + k8) = hi.u;
            *(uint4*)(smB_lo + n * LDT + k8) = lo.u;
        }
        __syncthreads();

#pragma unroll
        for (int kk = 0; kk < KC; kk += 16) {
            wmma::fragment<wmma::matrix_a, 16, 16, 16, __nv_bfloat16, wmma::row_major> ah[2], alx[2];
            wmma::fragment<wmma::matrix_b, 16, 16, 16, __nv_bfloat16, wmma::col_major> bh[2], blx[2];
#pragma unroll
            for (int mi = 0; mi < 2; mi++) {
                wmma::load_matrix_sync(ah[mi],  smA_hi + (wm * 32 + mi * 16) * LDT + kk, LDT);
                wmma::load_matrix_sync(alx[mi], smA_lo + (wm * 32 + mi * 16) * LDT + kk, LDT);
            }
#pragma unroll
            for (int ni = 0; ni < 2; ni++) {
                wmma::load_matrix_sync(bh[ni],  smB_hi + (wn * 32 + ni * 16) * LDT + kk, LDT);
                wmma::load_matrix_sync(blx[ni], smB_lo + (wn * 32 + ni * 16) * LDT + kk, LDT);
            }
#pragma unroll
            for (int mi = 0; mi < 2; mi++)
#pragma unroll
                for (int ni = 0; ni < 2; ni++) {
                    wmma::mma_sync(acc[mi][ni], ah[mi],  bh[ni],  acc[mi][ni]);
                    wmma::mma_sync(acc[mi][ni], alx[mi], bh[ni],  acc[mi][ni]);
                    wmma::mma_sync(acc[mi][ni], ah[mi],  blx[ni], acc[mi][ni]);
                }
        }
        __syncthreads();
    }

#pragma unroll
    for (int mi = 0; mi < 2; mi++)
#pragma unroll
        for (int ni = 0; ni < 2; ni++)
            wmma::store_matrix_sync(smC + (wm * 32 + mi * 16) * LDC + wn * 32 + ni * 16,
                                    acc[mi][ni], LDC, wmma::mem_row_major);
    __syncthreads();

    const float* al = attn_l + rel * DD;
    const float* ar = attn_r + rel * DD;
    const int c0 = lane * 4;
    const float al0 = __ldg(al + c0), al1 = __ldg(al + c0 + 1),
                al2 = __ldg(al + c0 + 2), al3 = __ldg(al + c0 + 3);
    const float ar0 = __ldg(ar + c0), ar1 = __ldg(ar + c0 + 1),
                ar2 = __ldg(ar + c0 + 2), ar3 = __ldg(ar + c0 + 3);

#pragma unroll
    for (int rr = 0; rr < 8; rr++) {
        int row  = wid * 8 + rr;
        int grow = row0 + row;
        float4 v = *(const float4*)(smC + row * LDC + c0);
        float el = v.x * al0 + v.y * al1 + v.z * al2 + v.w * al3;
        float er = v.x * ar0 + v.y * ar1 + v.z * ar2 + v.w * ar3;
#pragma unroll
        for (int off = 16; off > 0; off >>= 1) {
            el += __shfl_xor_sync(0xffffffffu, el, off);
            er += __shfl_xor_sync(0xffffffffu, er, off);
        }
        if (grow < NN) {
            *(float4*)(g_feat + ((size_t)rel * NN + grow) * DD + c0) = v;
            if (lane == 0) {
                g_el[rel * NN + grow] = el;
                g_er[rel * NN + grow] = er;
            }
        }
    }
}

// ---------------------------------------------------------------------------
// CSR build: zero -> histogram -> 3-kernel exclusive scan -> fill
// ---------------------------------------------------------------------------
__global__ void zero_cnt_kernel()
{
    int i = blockIdx.x * blockDim.x + threadIdx.x;
    if (i < RRNN) g_cnt[i] = 0;
}

__global__ void hist_kernel(const int* __restrict__ dst)
{
    int i = blockIdx.x * blockDim.x + threadIdx.x;
    if (i >= RR * EE) return;
    int r = i / EE;
    atomicAdd(g_cnt + r * NN + dst[i], 1);
}

// scan1: per-block (1024 elems) exclusive scan of g_cnt -> g_off, block sums
__global__ void scan1_kernel()
{
    __shared__ int s[256];
    const int tid  = threadIdx.x;
    const int base = blockIdx.x * 1024 + tid * 4;
    int v[4], run = 0;
#pragma unroll
    for (int j = 0; j < 4; j++) {
        v[j] = (base + j < RRNN) ? g_cnt[base + j] : 0;
        run += v[j];
    }
    s[tid] = run;
    __syncthreads();
    int val = run;
    for (int off = 1; off < 256; off <<= 1) {
        int x = (tid >= off) ? s[tid - off] : 0;
        __syncthreads();
        s[tid] = val = val + x;
        __syncthreads();
    }
    int excl = s[tid] - run;
#pragma unroll
    for (int j = 0; j < 4; j++) {
        if (base + j < RRNN) g_off[base + j] = excl;
        excl += v[j];
    }
    if (tid == 255) g_bsum[blockIdx.x] = s[255];
}

// scan2: single block exclusive scan over block sums
__global__ void scan2_kernel()
{
    __shared__ int s[512];
    const int tid = threadIdx.x;
    int v = (tid < NB1) ? g_bsum[tid] : 0;
    s[tid] = v;
    __syncthreads();
    int val = v;
    for (int off = 1; off < 512; off <<= 1) {
        int x = (tid >= off) ? s[tid - off] : 0;
        __syncthreads();
        s[tid] = val = val + x;
        __syncthreads();
    }
    if (tid < NB1) g_bsum[tid] = s[tid] - v;
}

// scan3: add block offsets, init fill cursors
__global__ void scan3_kernel()
{
    const int base = blockIdx.x * 1024 + threadIdx.x * 4;
    const int add  = g_bsum[blockIdx.x];
#pragma unroll
    for (int j = 0; j < 4; j++) {
        int i = base + j;
        if (i < RRNN) {
            int o = g_off[i] + add;
            g_off[i] = o;
            g_cur[i] = o;
        }
    }
}

__global__ void fill_kernel(const int* __restrict__ src, const int* __restrict__ dst)
{
    int i = blockIdx.x * blockDim.x + threadIdx.x;
    if (i >= RR * EE) return;
    int r = i / EE;
    int pos = atomicAdd(g_cur + r * NN + dst[i], 1);
    g_csrc[pos] = src[i];
}

// ---------------------------------------------------------------------------
// Fused softmax + aggregation: one warp per dst node, loops all relations.
// Gather-only (no atomics); single coalesced out write with bias folded in.
// No segment-max: |e| bounded small, softmax shift-invariant.
// ---------------------------------------------------------------------------
__global__ void __launch_bounds__(256) pass_agg_kernel(
    const float* __restrict__ bias, float* __restrict__ out)
{
    const int d    = (blockIdx.x * blockDim.x + threadIdx.x) >> 5;
    const int lane = threadIdx.x & 31;
    if (d >= NN) return;
    const int c0 = lane * 4;

    float4 acc;
    acc.x = (__ldg(bias + c0)     + __ldg(bias + DD + c0)     + __ldg(bias + 2 * DD + c0))     * (1.f / 3.f);
    acc.y = (__ldg(bias + c0 + 1) + __ldg(bias + DD + c0 + 1) + __ldg(bias + 2 * DD + c0 + 1)) * (1.f / 3.f);
    acc.z = (__ldg(bias + c0 + 2) + __ldg(bias + DD + c0 + 2) + __ldg(bias + 2 * DD + c0 + 2)) * (1.f / 3.f);
    acc.w = (__ldg(bias + c0 + 3) + __ldg(bias + DD + c0 + 3) + __ldg(bias + 2 * DD + c0 + 3)) * (1.f / 3.f);

#pragma unroll
    for (int r = 0; r < RR; r++) {
        const int idx = r * NN + d;
        const int beg = g_off[idx];
        const int end = g_cur[idx];       // fill cursor == end offset
        if (beg == end) continue;
        const float er_d = g_er[idx];

        // phase 1: exp-sum (lane-parallel over edges)
        float s = 0.f;
        for (int j = beg + lane; j < end; j += 32) {
            float e = g_el[r * NN + g_csrc[j]] + er_d;
            e = e >= 0.f ? e : 0.2f * e;
            s += __expf(e);
        }
#pragma unroll
        for (int off = 16; off > 0; off >>= 1)
            s += __shfl_xor_sync(0xffffffffu, s, off);
        const float inv = 1.0f / (s * 3.0f);

        // phase 2: weighted gather (edge-serial, warp-wide float4 rows)
        const float* featr = g_feat + (size_t)r * NN * DD;
        for (int j = beg; j < end; j++) {
            int sj = g_csrc[j];                       // broadcast load
            float e = g_el[r * NN + sj] + er_d;       // broadcast load
            e = e >= 0.f ? e : 0.2f * e;
            float w = __expf(e) * inv;
            const float4 f = *(const float4*)(featr + (size_t)sj * DD + c0);
            acc.x += w * f.x; acc.y += w * f.y; acc.z += w * f.z; acc.w += w * f.w;
        }
    }
    *(float4*)(out + (size_t)d * DD + c0) = acc;
}

// ---------------------------------------------------------------------------
// Launch
// ---------------------------------------------------------------------------
extern "C" void kernel_launch(void* const* d_in, const int* in_sizes, int n_in,
                              void* d_out, int out_size)
{
    const float* x    = (const float*)d_in[0];
    const int*   src  = (const int*)  d_in[1];
    const int*   dst  = (const int*)  d_in[2];
    const float* W    = (const float*)d_in[3];
    const float* al   = (const float*)d_in[4];
    const float* ar   = (const float*)d_in[5];
    const float* bias = (const float*)d_in[6];
    float* out = (float*)d_out;

    cudaFuncSetAttribute(gemm_feat_kernel, cudaFuncAttributeMaxDynamicSharedMemorySize, SM_TOT);

    // CSR build (independent of GEMM)
    zero_cnt_kernel<<<(RRNN + 255) / 256, 256>>>();
    hist_kernel<<<(RR * EE + 255) / 256, 256>>>(dst);
    scan1_kernel<<<NB1, 256>>>();
    scan2_kernel<<<1, 512>>>();
    scan3_kernel<<<NB1, 256>>>();
    fill_kernel<<<(RR * EE + 255) / 256, 256>>>(src, dst);

    // Projection + attention logits
    gemm_feat_kernel<<<dim3((NN + 127) / 128, RR), 512, SM_TOT>>>(x, W, al, ar);

    // Fused softmax + aggregation + bias + mean
    pass_agg_kernel<<<(NN * 32 + 255) / 256, 256>>>(bias, out);
}

// round 8
// speedup vs baseline: 1.4062x; 1.1261x over previous
#include <cuda_runtime.h>
#include <cuda_bf16.h>
#include <mma.h>
#include <math.h>
#include <stdint.h>

using namespace nvcuda;

// Problem constants
#define NN 100000
#define DD 128
#define EE 500000
#define RR 3
#define RRNN (RR * NN)                 // 300000
#define NB1  ((RRNN + 1023) / 1024)    // 293 scan blocks

// ---------------------------------------------------------------------------
// Static device scratch (allocation-free rule)
// ---------------------------------------------------------------------------
__device__ float g_feat[(size_t)RR * NN * DD];  // 153.6 MB
__device__ float g_el[RRNN];
__device__ float g_er[RRNN];
__device__ int   g_cnt[RRNN];
__device__ int   g_off[RRNN];
__device__ int   g_cur[RRNN];
__device__ int   g_bsum[NB1];
__device__ int   g_csrc[(size_t)RR * EE];

union Pack8 { __nv_bfloat16 h[8]; uint4 u; };

// ---------------------------------------------------------------------------
// GEMM: feat[r] = x @ W[r]^T via bf16x3 split wmma (m16n16k16).
// ONE CTA = one 128-row x tile, ALL 3 relations: A (hi/lo, full K=128) loaded
// and split once into smem; per relation, load W[r] (hi/lo, full K), run one
// k-loop, epilogue. Cuts x DRAM reads and A conversion work by 3x.
// smem: A 69632 + B 69632 + C stage 67584 = 206848 B (1 CTA/SM, 16 warps).
// ---------------------------------------------------------------------------
#define LDT   136                      // bf16 tile stride (elems), 272 B rows
#define LDC   132                      // C stage stride (floats)
#define TBF   (128 * LDT)              // elems per tile buffer
#define SM_A  0
#define SM_B  (2 * TBF * 2)            // after A hi+lo (bytes)
#define SM_C  (4 * TBF * 2)            // after B hi+lo (bytes)
#define SM_TOT (SM_C + 128 * LDC * 4)  // 206848 B

__device__ __forceinline__ void split8(const float* __restrict__ p, Pack8& hi, Pack8& lo)
{
    float4 v0 = __ldg((const float4*)p);
    float4 v1 = __ldg((const float4*)(p + 4));
    float wv[8] = {v0.x, v0.y, v0.z, v0.w, v1.x, v1.y, v1.z, v1.w};
#pragma unroll
    for (int j = 0; j < 8; j++) {
        __nv_bfloat16 h = __float2bfloat16(wv[j]);
        hi.h[j] = h;
        lo.h[j] = __float2bfloat16(wv[j] - __bfloat162float(h));
    }
}

__global__ void __launch_bounds__(512) gemm_feat_kernel(
    const float* __restrict__ x, const float* __restrict__ W,
    const float* __restrict__ attn_l, const float* __restrict__ attn_r)
{
    extern __shared__ char smraw[];
    __nv_bfloat16* smA_hi = (__nv_bfloat16*)(smraw + SM_A);
    __nv_bfloat16* smA_lo = smA_hi + TBF;
    __nv_bfloat16* smB_hi = (__nv_bfloat16*)(smraw + SM_B);
    __nv_bfloat16* smB_lo = smB_hi + TBF;
    float*         smC    = (float*)(smraw + SM_C);

    const int tid  = threadIdx.x;
    const int wid  = tid >> 5;
    const int lane = tid & 31;
    const int row0 = blockIdx.x * 128;
    const int wm   = wid >> 2;      // 0..3 : 32-row slab
    const int wn   = wid & 3;       // 0..3 : 32-col slab

    // --- Load A once: x rows fp32 -> bf16 hi/lo, full K=128 ---
#pragma unroll
    for (int t = 0; t < 4; t++) {
        int idx  = tid + t * 512;          // 0..2047
        int row  = idx >> 4;
        int k8   = (idx & 15) << 3;
        int grow = row0 + row;
        Pack8 hi, lo;
        if (grow < NN) {
            split8(x + (size_t)grow * DD + k8, hi, lo);
        } else {
            hi.u = make_uint4(0u, 0u, 0u, 0u); lo.u = hi.u;
        }
        *(uint4*)(smA_hi + row * LDT + k8) = hi.u;
        *(uint4*)(smA_lo + row * LDT + k8) = lo.u;
    }
    __syncthreads();

    for (int rel = 0; rel < RR; rel++) {
        // --- Load B: W[rel][n][k] fp32 -> bf16 hi/lo, full K ---
        const float* Wr = W + (size_t)rel * DD * DD;
#pragma unroll
        for (int t = 0; t < 4; t++) {
            int idx = tid + t * 512;
            int n   = idx >> 4;
            int k8  = (idx & 15) << 3;
            Pack8 hi, lo;
            split8(Wr + (size_t)n * DD + k8, hi, lo);
            *(uint4*)(smB_hi + n * LDT + k8) = hi.u;
            *(uint4*)(smB_lo + n * LDT + k8) = lo.u;
        }
        __syncthreads();   // also protects smC reads of previous relation

        wmma::fragment<wmma::accumulator, 16, 16, 16, float> acc[2][2];
#pragma unroll
        for (int mi = 0; mi < 2; mi++)
#pragma unroll
            for (int ni = 0; ni < 2; ni++) wmma::fill_fragment(acc[mi][ni], 0.0f);

        // Fused-term k-loop: 8 fragment loads feed 12 MMAs per step
#pragma unroll 2
        for (int kk = 0; kk < DD; kk += 16) {
            wmma::fragment<wmma::matrix_a, 16, 16, 16, __nv_bfloat16, wmma::row_major> ah[2], alx[2];
            wmma::fragment<wmma::matrix_b, 16, 16, 16, __nv_bfloat16, wmma::col_major> bh[2], blx[2];
#pragma unroll
            for (int mi = 0; mi < 2; mi++) {
                wmma::load_matrix_sync(ah[mi],  smA_hi + (wm * 32 + mi * 16) * LDT + kk, LDT);
                wmma::load_matrix_sync(alx[mi], smA_lo + (wm * 32 + mi * 16) * LDT + kk, LDT);
            }
#pragma unroll
            for (int ni = 0; ni < 2; ni++) {
                wmma::load_matrix_sync(bh[ni],  smB_hi + (wn * 32 + ni * 16) * LDT + kk, LDT);
                wmma::load_matrix_sync(blx[ni], smB_lo + (wn * 32 + ni * 16) * LDT + kk, LDT);
            }
#pragma unroll
            for (int mi = 0; mi < 2; mi++)
#pragma unroll
                for (int ni = 0; ni < 2; ni++) {
                    wmma::mma_sync(acc[mi][ni], ah[mi],  bh[ni],  acc[mi][ni]);
                    wmma::mma_sync(acc[mi][ni], alx[mi], bh[ni],  acc[mi][ni]);
                    wmma::mma_sync(acc[mi][ni], ah[mi],  blx[ni], acc[mi][ni]);
                }
        }

        // --- Epilogue: stage C in smem, write feat[rel] + el/er ---
#pragma unroll
        for (int mi = 0; mi < 2; mi++)
#pragma unroll
            for (int ni = 0; ni < 2; ni++)
                wmma::store_matrix_sync(smC + (wm * 32 + mi * 16) * LDC + wn * 32 + ni * 16,
                                        acc[mi][ni], LDC, wmma::mem_row_major);
        __syncthreads();

        const float* al = attn_l + rel * DD;
        const float* ar = attn_r + rel * DD;
        const int c0 = lane * 4;
        const float al0 = __ldg(al + c0), al1 = __ldg(al + c0 + 1),
                    al2 = __ldg(al + c0 + 2), al3 = __ldg(al + c0 + 3);
        const float ar0 = __ldg(ar + c0), ar1 = __ldg(ar + c0 + 1),
                    ar2 = __ldg(ar + c0 + 2), ar3 = __ldg(ar + c0 + 3);

#pragma unroll
        for (int rr = 0; rr < 8; rr++) {
            int row  = wid * 8 + rr;
            int grow = row0 + row;
            float4 v = *(const float4*)(smC + row * LDC + c0);
            float el = v.x * al0 + v.y * al1 + v.z * al2 + v.w * al3;
            float er = v.x * ar0 + v.y * ar1 + v.z * ar2 + v.w * ar3;
#pragma unroll
            for (int off = 16; off > 0; off >>= 1) {
                el += __shfl_xor_sync(0xffffffffu, el, off);
                er += __shfl_xor_sync(0xffffffffu, er, off);
            }
            if (grow < NN) {
                *(float4*)(g_feat + ((size_t)rel * NN + grow) * DD + c0) = v;
                if (lane == 0) {
                    g_el[rel * NN + grow] = el;
                    g_er[rel * NN + grow] = er;
                }
            }
        }
        // next relation's B-load __syncthreads protects smC/smB reuse
    }
}

// ---------------------------------------------------------------------------
// CSR build: zero -> histogram -> 3-kernel exclusive scan -> fill
// ---------------------------------------------------------------------------
__global__ void zero_cnt_kernel()
{
    int i = blockIdx.x * blockDim.x + threadIdx.x;
    if (i < RRNN) g_cnt[i] = 0;
}

__global__ void hist_kernel(const int* __restrict__ dst)
{
    int i = blockIdx.x * blockDim.x + threadIdx.x;
    if (i >= RR * EE) return;
    int r = i / EE;
    atomicAdd(g_cnt + r * NN + dst[i], 1);
}

__global__ void scan1_kernel()
{
    __shared__ int s[256];
    const int tid  = threadIdx.x;
    const int base = blockIdx.x * 1024 + tid * 4;
    int v[4], run = 0;
#pragma unroll
    for (int j = 0; j < 4; j++) {
        v[j] = (base + j < RRNN) ? g_cnt[base + j] : 0;
        run += v[j];
    }
    s[tid] = run;
    __syncthreads();
    int val = run;
    for (int off = 1; off < 256; off <<= 1) {
        int x = (tid >= off) ? s[tid - off] : 0;
        __syncthreads();
        s[tid] = val = val + x;
        __syncthreads();
    }
    int excl = s[tid] - run;
#pragma unroll
    for (int j = 0; j < 4; j++) {
        if (base + j < RRNN) g_off[base + j] = excl;
        excl += v[j];
    }
    if (tid == 255) g_bsum[blockIdx.x] = s[255];
}

__global__ void scan2_kernel()
{
    __shared__ int s[512];
    const int tid = threadIdx.x;
    int v = (tid < NB1) ? g_bsum[tid] : 0;
    s[tid] = v;
    __syncthreads();
    int val = v;
    for (int off = 1; off < 512; off <<= 1) {
        int x = (tid >= off) ? s[tid - off] : 0;
        __syncthreads();
        s[tid] = val = val + x;
        __syncthreads();
    }
    if (tid < NB1) g_bsum[tid] = s[tid] - v;
}

__global__ void scan3_kernel()
{
    const int base = blockIdx.x * 1024 + threadIdx.x * 4;
    const int add  = g_bsum[blockIdx.x];
#pragma unroll
    for (int j = 0; j < 4; j++) {
        int i = base + j;
        if (i < RRNN) {
            int o = g_off[i] + add;
            g_off[i] = o;
            g_cur[i] = o;
        }
    }
}

__global__ void fill_kernel(const int* __restrict__ src, const int* __restrict__ dst)
{
    int i = blockIdx.x * blockDim.x + threadIdx.x;
    if (i >= RR * EE) return;
    int r = i / EE;
    int pos = atomicAdd(g_cur + r * NN + dst[i], 1);
    g_csrc[pos] = src[i];
}

// ---------------------------------------------------------------------------
// Fused softmax + aggregation: one warp per dst node, loops all relations.
// Gather-only (no atomics); coalesced out write with bias folded in.
// ---------------------------------------------------------------------------
__global__ void __launch_bounds__(256) pass_agg_kernel(
    const float* __restrict__ bias, float* __restrict__ out)
{
    const int d    = (blockIdx.x * blockDim.x + threadIdx.x) >> 5;
    const int lane = threadIdx.x & 31;
    if (d >= NN) return;
    const int c0 = lane * 4;

    float4 acc;
    acc.x = (__ldg(bias + c0)     + __ldg(bias + DD + c0)     + __ldg(bias + 2 * DD + c0))     * (1.f / 3.f);
    acc.y = (__ldg(bias + c0 + 1) + __ldg(bias + DD + c0 + 1) + __ldg(bias + 2 * DD + c0 + 1)) * (1.f / 3.f);
    acc.z = (__ldg(bias + c0 + 2) + __ldg(bias + DD + c0 + 2) + __ldg(bias + 2 * DD + c0 + 2)) * (1.f / 3.f);
    acc.w = (__ldg(bias + c0 + 3) + __ldg(bias + DD + c0 + 3) + __ldg(bias + 2 * DD + c0 + 3)) * (1.f / 3.f);

#pragma unroll
    for (int r = 0; r < RR; r++) {
        const int idx = r * NN + d;
        const int beg = g_off[idx];
        const int end = g_cur[idx];
        if (beg == end) continue;
        const float er_d = g_er[idx];

        // phase 1: exp-sum (lane-parallel over edges)
        float s = 0.f;
        for (int j = beg + lane; j < end; j += 32) {
            float e = g_el[r * NN + g_csrc[j]] + er_d;
            e = e >= 0.f ? e : 0.2f * e;
            s += __expf(e);
        }
#pragma unroll
        for (int off = 16; off > 0; off >>= 1)
            s += __shfl_xor_sync(0xffffffffu, s, off);
        const float inv = 1.0f / (s * 3.0f);

        // phase 2: weighted gather, 2-edge unrolled for MLP
        const float* featr = g_feat + (size_t)r * NN * DD;
        int j = beg;
        for (; j + 1 < end; j += 2) {
            int s0 = g_csrc[j], s1 = g_csrc[j + 1];
            float e0 = g_el[r * NN + s0] + er_d;
            float e1 = g_el[r * NN + s1] + er_d;
            e0 = e0 >= 0.f ? e0 : 0.2f * e0;
            e1 = e1 >= 0.f ? e1 : 0.2f * e1;
            float w0 = __expf(e0) * inv;
            float w1 = __expf(e1) * inv;
            const float4 f0 = *(const float4*)(featr + (size_t)s0 * DD + c0);
            const float4 f1 = *(const float4*)(featr + (size_t)s1 * DD + c0);
            acc.x += w0 * f0.x + w1 * f1.x;
            acc.y += w0 * f0.y + w1 * f1.y;
            acc.z += w0 * f0.z + w1 * f1.z;
            acc.w += w0 * f0.w + w1 * f1.w;
        }
        if (j < end) {
            int sj = g_csrc[j];
            float e = g_el[r * NN + sj] + er_d;
            e = e >= 0.f ? e : 0.2f * e;
            float w = __expf(e) * inv;
            const float4 f = *(const float4*)(featr + (size_t)sj * DD + c0);
            acc.x += w * f.x; acc.y += w * f.y; acc.z += w * f.z; acc.w += w * f.w;
        }
    }
    *(float4*)(out + (size_t)d * DD + c0) = acc;
}

// ---------------------------------------------------------------------------
// Launch
// ---------------------------------------------------------------------------
extern "C" void kernel_launch(void* const* d_in, const int* in_sizes, int n_in,
                              void* d_out, int out_size)
{
    const float* x    = (const float*)d_in[0];
    const int*   src  = (const int*)  d_in[1];
    const int*   dst  = (const int*)  d_in[2];
    const float* W    = (const float*)d_in[3];
    const float* al   = (const float*)d_in[4];
    const float* ar   = (const float*)d_in[5];
    const float* bias = (const float*)d_in[6];
    float* out = (float*)d_out;

    cudaFuncSetAttribute(gemm_feat_kernel, cudaFuncAttributeMaxDynamicSharedMemorySize, SM_TOT);

    // CSR build (independent of GEMM)
    zero_cnt_kernel<<<(RRNN + 255) / 256, 256>>>();
    hist_kernel<<<(RR * EE + 255) / 256, 256>>>(dst);
    scan1_kernel<<<NB1, 256>>>();
    scan2_kernel<<<1, 512>>>();
    scan3_kernel<<<NB1, 256>>>();
    fill_kernel<<<(RR * EE + 255) / 256, 256>>>(src, dst);

    // Projection + attention logits (all relations per CTA)
    gemm_feat_kernel<<<(NN + 127) / 128, 512, SM_TOT>>>(x, W, al, ar);

    // Fused softmax + aggregation + bias + mean
    pass_agg_kernel<<<(NN * 32 + 255) / 256, 256>>>(bias, out);
}

// round 9
// speedup vs baseline: 1.5033x; 1.0690x over previous
#include <cuda_runtime.h>
#include <cuda_bf16.h>
#include <cuda_fp16.h>
#include <mma.h>
#include <math.h>
#include <stdint.h>

using namespace nvcuda;

// Problem constants
#define NN 100000
#define DD 128
#define EE 500000
#define RR 3
#define RRNN (RR * NN)                 // 300000
#define NB1  ((RRNN + 1023) / 1024)    // 293 scan blocks

// ---------------------------------------------------------------------------
// Static device scratch (allocation-free rule)
// ---------------------------------------------------------------------------
__device__ __half g_feat[(size_t)RR * NN * DD];  // 76.8 MB (fp16 halves gather)
__device__ float  g_el[RRNN];
__device__ float  g_er[RRNN];
__device__ int    g_cnt[RRNN];
__device__ int    g_off[RRNN];
__device__ int    g_cur[RRNN];
__device__ int    g_bsum[NB1];
__device__ int    g_csrc[(size_t)RR * EE];

union Pack8 { __nv_bfloat16 h[8]; uint4 u; };

// ---------------------------------------------------------------------------
// GEMM: feat[r] = x @ W[r]^T via bf16x3 split wmma (m16n16k16).
// ONE CTA = one 128-row x tile, ALL 3 relations (A loaded/split once).
// Epilogue: stage C in smem, write feat[rel] (fp16) + el/er (fp32).
// ---------------------------------------------------------------------------
#define LDT   136                      // bf16 tile stride (elems)
#define LDC   132                      // C stage stride (floats)
#define TBF   (128 * LDT)
#define SM_A  0
#define SM_B  (2 * TBF * 2)
#define SM_C  (4 * TBF * 2)
#define SM_TOT (SM_C + 128 * LDC * 4)  // 206848 B

__device__ __forceinline__ void split8(const float* __restrict__ p, Pack8& hi, Pack8& lo)
{
    float4 v0 = __ldg((const float4*)p);
    float4 v1 = __ldg((const float4*)(p + 4));
    float wv[8] = {v0.x, v0.y, v0.z, v0.w, v1.x, v1.y, v1.z, v1.w};
#pragma unroll
    for (int j = 0; j < 8; j++) {
        __nv_bfloat16 h = __float2bfloat16(wv[j]);
        hi.h[j] = h;
        lo.h[j] = __float2bfloat16(wv[j] - __bfloat162float(h));
    }
}

__global__ void __launch_bounds__(512) gemm_feat_kernel(
    const float* __restrict__ x, const float* __restrict__ W,
    const float* __restrict__ attn_l, const float* __restrict__ attn_r)
{
    extern __shared__ char smraw[];
    __nv_bfloat16* smA_hi = (__nv_bfloat16*)(smraw + SM_A);
    __nv_bfloat16* smA_lo = smA_hi + TBF;
    __nv_bfloat16* smB_hi = (__nv_bfloat16*)(smraw + SM_B);
    __nv_bfloat16* smB_lo = smB_hi + TBF;
    float*         smC    = (float*)(smraw + SM_C);

    const int tid  = threadIdx.x;
    const int wid  = tid >> 5;
    const int lane = tid & 31;
    const int row0 = blockIdx.x * 128;
    const int wm   = wid >> 2;
    const int wn   = wid & 3;

    // --- Load A once: x rows fp32 -> bf16 hi/lo, full K=128 ---
#pragma unroll
    for (int t = 0; t < 4; t++) {
        int idx  = tid + t * 512;
        int row  = idx >> 4;
        int k8   = (idx & 15) << 3;
        int grow = row0 + row;
        Pack8 hi, lo;
        if (grow < NN) {
            split8(x + (size_t)grow * DD + k8, hi, lo);
        } else {
            hi.u = make_uint4(0u, 0u, 0u, 0u); lo.u = hi.u;
        }
        *(uint4*)(smA_hi + row * LDT + k8) = hi.u;
        *(uint4*)(smA_lo + row * LDT + k8) = lo.u;
    }
    __syncthreads();

    for (int rel = 0; rel < RR; rel++) {
        const float* Wr = W + (size_t)rel * DD * DD;
#pragma unroll
        for (int t = 0; t < 4; t++) {
            int idx = tid + t * 512;
            int n   = idx >> 4;
            int k8  = (idx & 15) << 3;
            Pack8 hi, lo;
            split8(Wr + (size_t)n * DD + k8, hi, lo);
            *(uint4*)(smB_hi + n * LDT + k8) = hi.u;
            *(uint4*)(smB_lo + n * LDT + k8) = lo.u;
        }
        __syncthreads();   // also protects smC reads of previous relation

        wmma::fragment<wmma::accumulator, 16, 16, 16, float> acc[2][2];
#pragma unroll
        for (int mi = 0; mi < 2; mi++)
#pragma unroll
            for (int ni = 0; ni < 2; ni++) wmma::fill_fragment(acc[mi][ni], 0.0f);

#pragma unroll 2
        for (int kk = 0; kk < DD; kk += 16) {
            wmma::fragment<wmma::matrix_a, 16, 16, 16, __nv_bfloat16, wmma::row_major> ah[2], alx[2];
            wmma::fragment<wmma::matrix_b, 16, 16, 16, __nv_bfloat16, wmma::col_major> bh[2], blx[2];
#pragma unroll
            for (int mi = 0; mi < 2; mi++) {
                wmma::load_matrix_sync(ah[mi],  smA_hi + (wm * 32 + mi * 16) * LDT + kk, LDT);
                wmma::load_matrix_sync(alx[mi], smA_lo + (wm * 32 + mi * 16) * LDT + kk, LDT);
            }
#pragma unroll
            for (int ni = 0; ni < 2; ni++) {
                wmma::load_matrix_sync(bh[ni],  smB_hi + (wn * 32 + ni * 16) * LDT + kk, LDT);
                wmma::load_matrix_sync(blx[ni], smB_lo + (wn * 32 + ni * 16) * LDT + kk, LDT);
            }
#pragma unroll
            for (int mi = 0; mi < 2; mi++)
#pragma unroll
                for (int ni = 0; ni < 2; ni++) {
                    wmma::mma_sync(acc[mi][ni], ah[mi],  bh[ni],  acc[mi][ni]);
                    wmma::mma_sync(acc[mi][ni], alx[mi], bh[ni],  acc[mi][ni]);
                    wmma::mma_sync(acc[mi][ni], ah[mi],  blx[ni], acc[mi][ni]);
                }
        }

#pragma unroll
        for (int mi = 0; mi < 2; mi++)
#pragma unroll
            for (int ni = 0; ni < 2; ni++)
                wmma::store_matrix_sync(smC + (wm * 32 + mi * 16) * LDC + wn * 32 + ni * 16,
                                        acc[mi][ni], LDC, wmma::mem_row_major);
        __syncthreads();

        const float* al = attn_l + rel * DD;
        const float* ar = attn_r + rel * DD;
        const int c0 = lane * 4;
        const float al0 = __ldg(al + c0), al1 = __ldg(al + c0 + 1),
                    al2 = __ldg(al + c0 + 2), al3 = __ldg(al + c0 + 3);
        const float ar0 = __ldg(ar + c0), ar1 = __ldg(ar + c0 + 1),
                    ar2 = __ldg(ar + c0 + 2), ar3 = __ldg(ar + c0 + 3);

#pragma unroll
        for (int rr = 0; rr < 8; rr++) {
            int row  = wid * 8 + rr;
            int grow = row0 + row;
            float4 v = *(const float4*)(smC + row * LDC + c0);
            float el = v.x * al0 + v.y * al1 + v.z * al2 + v.w * al3;
            float er = v.x * ar0 + v.y * ar1 + v.z * ar2 + v.w * ar3;
#pragma unroll
            for (int off = 16; off > 0; off >>= 1) {
                el += __shfl_xor_sync(0xffffffffu, el, off);
                er += __shfl_xor_sync(0xffffffffu, er, off);
            }
            if (grow < NN) {
                // fp16 feat write: 4 halves per lane (8 B), coalesced
                __half2 h01 = __float22half2_rn(make_float2(v.x, v.y));
                __half2 h23 = __float22half2_rn(make_float2(v.z, v.w));
                uint2 pk = make_uint2(*(uint32_t*)&h01, *(uint32_t*)&h23);
                *(uint2*)(g_feat + ((size_t)rel * NN + grow) * DD + c0) = pk;
                if (lane == 0) {
                    g_el[rel * NN + grow] = el;
                    g_er[rel * NN + grow] = er;
                }
            }
        }
    }
}

// ---------------------------------------------------------------------------
// CSR build: zero -> histogram -> 3-kernel exclusive scan -> fill
// ---------------------------------------------------------------------------
__global__ void zero_cnt_kernel()
{
    int i = blockIdx.x * blockDim.x + threadIdx.x;
    if (i < RRNN) g_cnt[i] = 0;
}

__global__ void hist_kernel(const int* __restrict__ dst)
{
    int i = blockIdx.x * blockDim.x + threadIdx.x;
    if (i >= RR * EE) return;
    int r = i / EE;
    atomicAdd(g_cnt + r * NN + dst[i], 1);
}

__global__ void scan1_kernel()
{
    __shared__ int s[256];
    const int tid  = threadIdx.x;
    const int base = blockIdx.x * 1024 + tid * 4;
    int v[4], run = 0;
#pragma unroll
    for (int j = 0; j < 4; j++) {
        v[j] = (base + j < RRNN) ? g_cnt[base + j] : 0;
        run += v[j];
    }
    s[tid] = run;
    __syncthreads();
    int val = run;
    for (int off = 1; off < 256; off <<= 1) {
        int x = (tid >= off) ? s[tid - off] : 0;
        __syncthreads();
        s[tid] = val = val + x;
        __syncthreads();
    }
    int excl = s[tid] - run;
#pragma unroll
    for (int j = 0; j < 4; j++) {
        if (base + j < RRNN) g_off[base + j] = excl;
        excl += v[j];
    }
    if (tid == 255) g_bsum[blockIdx.x] = s[255];
}

__global__ void scan2_kernel()
{
    __shared__ int s[512];
    const int tid = threadIdx.x;
    int v = (tid < NB1) ? g_bsum[tid] : 0;
    s[tid] = v;
    __syncthreads();
    int val = v;
    for (int off = 1; off < 512; off <<= 1) {
        int x = (tid >= off) ? s[tid - off] : 0;
        __syncthreads();
        s[tid] = val = val + x;
        __syncthreads();
    }
    if (tid < NB1) g_bsum[tid] = s[tid] - v;
}

__global__ void scan3_kernel()
{
    const int base = blockIdx.x * 1024 + threadIdx.x * 4;
    const int add  = g_bsum[blockIdx.x];
#pragma unroll
    for (int j = 0; j < 4; j++) {
        int i = base + j;
        if (i < RRNN) {
            int o = g_off[i] + add;
            g_off[i] = o;
            g_cur[i] = o;
        }
    }
}

__global__ void fill_kernel(const int* __restrict__ src, const int* __restrict__ dst)
{
    int i = blockIdx.x * blockDim.x + threadIdx.x;
    if (i >= RR * EE) return;
    int r = i / EE;
    int pos = atomicAdd(g_cur + r * NN + dst[i], 1);
    g_csrc[pos] = src[i];
}

// ---------------------------------------------------------------------------
// Fused softmax + aggregation: one warp per dst node, loops all relations.
// Gather-only; fp16 feat rows (256 B/edge); single coalesced out write.
// ---------------------------------------------------------------------------
__global__ void __launch_bounds__(256) pass_agg_kernel(
    const float* __restrict__ bias, float* __restrict__ out)
{
    const int d    = (blockIdx.x * blockDim.x + threadIdx.x) >> 5;
    const int lane = threadIdx.x & 31;
    if (d >= NN) return;
    const int c0 = lane * 4;

    float4 acc;
    acc.x = (__ldg(bias + c0)     + __ldg(bias + DD + c0)     + __ldg(bias + 2 * DD + c0))     * (1.f / 3.f);
    acc.y = (__ldg(bias + c0 + 1) + __ldg(bias + DD + c0 + 1) + __ldg(bias + 2 * DD + c0 + 1)) * (1.f / 3.f);
    acc.z = (__ldg(bias + c0 + 2) + __ldg(bias + DD + c0 + 2) + __ldg(bias + 2 * DD + c0 + 2)) * (1.f / 3.f);
    acc.w = (__ldg(bias + c0 + 3) + __ldg(bias + DD + c0 + 3) + __ldg(bias + 2 * DD + c0 + 3)) * (1.f / 3.f);

#pragma unroll
    for (int r = 0; r < RR; r++) {
        const int idx = r * NN + d;
        const int beg = g_off[idx];
        const int end = g_cur[idx];
        if (beg == end) continue;
        const float er_d = g_er[idx];

        // phase 1: exp-sum (lane-parallel over edges)
        float s = 0.f;
        for (int j = beg + lane; j < end; j += 32) {
            float e = g_el[r * NN + g_csrc[j]] + er_d;
            e = e >= 0.f ? e : 0.2f * e;
            s += __expf(e);
        }
#pragma unroll
        for (int off = 16; off > 0; off >>= 1)
            s += __shfl_xor_sync(0xffffffffu, s, off);
        const float inv = 1.0f / (s * 3.0f);

        // phase 2: weighted gather of fp16 rows, 2-edge unrolled for MLP
        const __half* featr = g_feat + (size_t)r * NN * DD;
        int j = beg;
        for (; j + 1 < end; j += 2) {
            int s0 = g_csrc[j], s1 = g_csrc[j + 1];
            float e0 = g_el[r * NN + s0] + er_d;
            float e1 = g_el[r * NN + s1] + er_d;
            e0 = e0 >= 0.f ? e0 : 0.2f * e0;
            e1 = e1 >= 0.f ? e1 : 0.2f * e1;
            float w0 = __expf(e0) * inv;
            float w1 = __expf(e1) * inv;
            uint2 p0 = *(const uint2*)(featr + (size_t)s0 * DD + c0);
            uint2 p1 = *(const uint2*)(featr + (size_t)s1 * DD + c0);
            float2 a01 = __half22float2(*(__half2*)&p0.x);
            float2 a23 = __half22float2(*(__half2*)&p0.y);
            float2 b01 = __half22float2(*(__half2*)&p1.x);
            float2 b23 = __half22float2(*(__half2*)&p1.y);
            acc.x += w0 * a01.x + w1 * b01.x;
            acc.y += w0 * a01.y + w1 * b01.y;
            acc.z += w0 * a23.x + w1 * b23.x;
            acc.w += w0 * a23.y + w1 * b23.y;
        }
        if (j < end) {
            int sj = g_csrc[j];
            float e = g_el[r * NN + sj] + er_d;
            e = e >= 0.f ? e : 0.2f * e;
            float w = __expf(e) * inv;
            uint2 p0 = *(const uint2*)(featr + (size_t)sj * DD + c0);
            float2 a01 = __half22float2(*(__half2*)&p0.x);
            float2 a23 = __half22float2(*(__half2*)&p0.y);
            acc.x += w * a01.x; acc.y += w * a01.y;
            acc.z += w * a23.x; acc.w += w * a23.y;
        }
    }
    *(float4*)(out + (size_t)d * DD + c0) = acc;
}

// ---------------------------------------------------------------------------
// Launch
// ---------------------------------------------------------------------------
extern "C" void kernel_launch(void* const* d_in, const int* in_sizes, int n_in,
                              void* d_out, int out_size)
{
    const float* x    = (const float*)d_in[0];
    const int*   src  = (const int*)  d_in[1];
    const int*   dst  = (const int*)  d_in[2];
    const float* W    = (const float*)d_in[3];
    const float* al   = (const float*)d_in[4];
    const float* ar   = (const float*)d_in[5];
    const float* bias = (const float*)d_in[6];
    float* out = (float*)d_out;

    cudaFuncSetAttribute(gemm_feat_kernel, cudaFuncAttributeMaxDynamicSharedMemorySize, SM_TOT);

    // CSR build (independent of GEMM)
    zero_cnt_kernel<<<(RRNN + 255) / 256, 256>>>();
    hist_kernel<<<(RR * EE + 255) / 256, 256>>>(dst);
    scan1_kernel<<<NB1, 256>>>();
    scan2_kernel<<<1, 512>>>();
    scan3_kernel<<<NB1, 256>>>();
    fill_kernel<<<(RR * EE + 255) / 256, 256>>>(src, dst);

    // Projection + attention logits (all relations per CTA)
    gemm_feat_kernel<<<(NN + 127) / 128, 512, SM_TOT>>>(x, W, al, ar);

    // Fused softmax + aggregation + bias + mean
    pass_agg_kernel<<<(NN * 32 + 255) / 256, 256>>>(bias, out);
}

// round 10
// speedup vs baseline: 1.6217x; 1.0788x over previous
#include <cuda_runtime.h>
#include <cuda_bf16.h>
#include <cuda_fp16.h>
#include <mma.h>
#include <math.h>
#include <stdint.h>

using namespace nvcuda;

// Problem constants
#define NN 100000
#define DD 128
#define EE 500000
#define RR 3
#define RRNN (RR * NN)                 // 300000
#define NB1  ((RRNN + 1023) / 1024)    // 293 scan blocks

// ---------------------------------------------------------------------------
// Static device scratch (allocation-free rule)
// ---------------------------------------------------------------------------
__device__ __half g_feat[(size_t)RR * NN * DD];  // 76.8 MB (fp16 gather)
__device__ float  g_el[RRNN];
__device__ float  g_er[RRNN];
__device__ int    g_cnt[RRNN];
__device__ int    g_off[RRNN];
__device__ int    g_cur[RRNN];
__device__ int    g_bsum[NB1];
__device__ int    g_csrc[(size_t)RR * EE];
__device__ float  g_wcsr[(size_t)RR * EE];       // per-edge exp(e), CSR order

union Pack8 { __nv_bfloat16 h[8]; uint4 u; };

// ---------------------------------------------------------------------------
// GEMM: feat[r] = x @ W[r]^T via bf16x3 split wmma (m16n16k16).
// ONE CTA = one 128-row x tile, ALL 3 relations (A loaded/split once).
// Epilogue: stage C in smem, write feat[rel] (fp16) + el/er (fp32).
// ---------------------------------------------------------------------------
#define LDT   136
#define LDC   132
#define TBF   (128 * LDT)
#define SM_A  0
#define SM_B  (2 * TBF * 2)
#define SM_C  (4 * TBF * 2)
#define SM_TOT (SM_C + 128 * LDC * 4)  // 206848 B

__device__ __forceinline__ void split8(const float* __restrict__ p, Pack8& hi, Pack8& lo)
{
    float4 v0 = __ldg((const float4*)p);
    float4 v1 = __ldg((const float4*)(p + 4));
    float wv[8] = {v0.x, v0.y, v0.z, v0.w, v1.x, v1.y, v1.z, v1.w};
#pragma unroll
    for (int j = 0; j < 8; j++) {
        __nv_bfloat16 h = __float2bfloat16(wv[j]);
        hi.h[j] = h;
        lo.h[j] = __float2bfloat16(wv[j] - __bfloat162float(h));
    }
}

__global__ void __launch_bounds__(512) gemm_feat_kernel(
    const float* __restrict__ x, const float* __restrict__ W,
    const float* __restrict__ attn_l, const float* __restrict__ attn_r)
{
    extern __shared__ char smraw[];
    __nv_bfloat16* smA_hi = (__nv_bfloat16*)(smraw + SM_A);
    __nv_bfloat16* smA_lo = smA_hi + TBF;
    __nv_bfloat16* smB_hi = (__nv_bfloat16*)(smraw + SM_B);
    __nv_bfloat16* smB_lo = smB_hi + TBF;
    float*         smC    = (float*)(smraw + SM_C);

    const int tid  = threadIdx.x;
    const int wid  = tid >> 5;
    const int lane = tid & 31;
    const int row0 = blockIdx.x * 128;
    const int wm   = wid >> 2;
    const int wn   = wid & 3;

    // --- Load A once: x rows fp32 -> bf16 hi/lo, full K=128 ---
#pragma unroll
    for (int t = 0; t < 4; t++) {
        int idx  = tid + t * 512;
        int row  = idx >> 4;
        int k8   = (idx & 15) << 3;
        int grow = row0 + row;
        Pack8 hi, lo;
        if (grow < NN) {
            split8(x + (size_t)grow * DD + k8, hi, lo);
        } else {
            hi.u = make_uint4(0u, 0u, 0u, 0u); lo.u = hi.u;
        }
        *(uint4*)(smA_hi + row * LDT + k8) = hi.u;
        *(uint4*)(smA_lo + row * LDT + k8) = lo.u;
    }
    __syncthreads();

    for (int rel = 0; rel < RR; rel++) {
        const float* Wr = W + (size_t)rel * DD * DD;
#pragma unroll
        for (int t = 0; t < 4; t++) {
            int idx = tid + t * 512;
            int n   = idx >> 4;
            int k8  = (idx & 15) << 3;
            Pack8 hi, lo;
            split8(Wr + (size_t)n * DD + k8, hi, lo);
            *(uint4*)(smB_hi + n * LDT + k8) = hi.u;
            *(uint4*)(smB_lo + n * LDT + k8) = lo.u;
        }
        __syncthreads();   // also protects smC reads of previous relation

        wmma::fragment<wmma::accumulator, 16, 16, 16, float> acc[2][2];
#pragma unroll
        for (int mi = 0; mi < 2; mi++)
#pragma unroll
            for (int ni = 0; ni < 2; ni++) wmma::fill_fragment(acc[mi][ni], 0.0f);

#pragma unroll 2
        for (int kk = 0; kk < DD; kk += 16) {
            wmma::fragment<wmma::matrix_a, 16, 16, 16, __nv_bfloat16, wmma::row_major> ah[2], alx[2];
            wmma::fragment<wmma::matrix_b, 16, 16, 16, __nv_bfloat16, wmma::col_major> bh[2], blx[2];
#pragma unroll
            for (int mi = 0; mi < 2; mi++) {
                wmma::load_matrix_sync(ah[mi],  smA_hi + (wm * 32 + mi * 16) * LDT + kk, LDT);
                wmma::load_matrix_sync(alx[mi], smA_lo + (wm * 32 + mi * 16) * LDT + kk, LDT);
            }
#pragma unroll
            for (int ni = 0; ni < 2; ni++) {
                wmma::load_matrix_sync(bh[ni],  smB_hi + (wn * 32 + ni * 16) * LDT + kk, LDT);
                wmma::load_matrix_sync(blx[ni], smB_lo + (wn * 32 + ni * 16) * LDT + kk, LDT);
            }
#pragma unroll
            for (int mi = 0; mi < 2; mi++)
#pragma unroll
                for (int ni = 0; ni < 2; ni++) {
                    wmma::mma_sync(acc[mi][ni], ah[mi],  bh[ni],  acc[mi][ni]);
                    wmma::mma_sync(acc[mi][ni], alx[mi], bh[ni],  acc[mi][ni]);
                    wmma::mma_sync(acc[mi][ni], ah[mi],  blx[ni], acc[mi][ni]);
                }
        }

#pragma unroll
        for (int mi = 0; mi < 2; mi++)
#pragma unroll
            for (int ni = 0; ni < 2; ni++)
                wmma::store_matrix_sync(smC + (wm * 32 + mi * 16) * LDC + wn * 32 + ni * 16,
                                        acc[mi][ni], LDC, wmma::mem_row_major);
        __syncthreads();

        const float* al = attn_l + rel * DD;
        const float* ar = attn_r + rel * DD;
        const int c0 = lane * 4;
        const float al0 = __ldg(al + c0), al1 = __ldg(al + c0 + 1),
                    al2 = __ldg(al + c0 + 2), al3 = __ldg(al + c0 + 3);
        const float ar0 = __ldg(ar + c0), ar1 = __ldg(ar + c0 + 1),
                    ar2 = __ldg(ar + c0 + 2), ar3 = __ldg(ar + c0 + 3);

#pragma unroll
        for (int rr = 0; rr < 8; rr++) {
            int row  = wid * 8 + rr;
            int grow = row0 + row;
            float4 v = *(const float4*)(smC + row * LDC + c0);
            float el = v.x * al0 + v.y * al1 + v.z * al2 + v.w * al3;
            float er = v.x * ar0 + v.y * ar1 + v.z * ar2 + v.w * ar3;
#pragma unroll
            for (int off = 16; off > 0; off >>= 1) {
                el += __shfl_xor_sync(0xffffffffu, el, off);
                er += __shfl_xor_sync(0xffffffffu, er, off);
            }
            if (grow < NN) {
                __half2 h01 = __float22half2_rn(make_float2(v.x, v.y));
                __half2 h23 = __float22half2_rn(make_float2(v.z, v.w));
                uint2 pk = make_uint2(*(uint32_t*)&h01, *(uint32_t*)&h23);
                *(uint2*)(g_feat + ((size_t)rel * NN + grow) * DD + c0) = pk;
                if (lane == 0) {
                    g_el[rel * NN + grow] = el;
                    g_er[rel * NN + grow] = er;
                }
            }
        }
    }
}

// ---------------------------------------------------------------------------
// CSR build: zero -> histogram -> scan1 -> scan23(merged)
// ---------------------------------------------------------------------------
__global__ void zero_cnt_kernel()
{
    int i = blockIdx.x * blockDim.x + threadIdx.x;
    if (i < RRNN) g_cnt[i] = 0;
}

__global__ void hist_kernel(const int* __restrict__ dst)
{
    int i = blockIdx.x * blockDim.x + threadIdx.x;
    if (i >= RR * EE) return;
    int r = i / EE;
    atomicAdd(g_cnt + r * NN + dst[i], 1);
}

__global__ void scan1_kernel()
{
    __shared__ int s[256];
    const int tid  = threadIdx.x;
    const int base = blockIdx.x * 1024 + tid * 4;
    int v[4], run = 0;
#pragma unroll
    for (int j = 0; j < 4; j++) {
        v[j] = (base + j < RRNN) ? g_cnt[base + j] : 0;
        run += v[j];
    }
    s[tid] = run;
    __syncthreads();
    int val = run;
    for (int off = 1; off < 256; off <<= 1) {
        int x = (tid >= off) ? s[tid - off] : 0;
        __syncthreads();
        s[tid] = val = val + x;
        __syncthreads();
    }
    int excl = s[tid] - run;
#pragma unroll
    for (int j = 0; j < 4; j++) {
        if (base + j < RRNN) g_off[base + j] = excl;
        excl += v[j];
    }
    if (tid == 255) g_bsum[blockIdx.x] = s[255];
}

// scan23: each block sums bsum prefix itself, then adds + inits cursors
__global__ void scan23_kernel()
{
    __shared__ int wsum[8];
    const int tid = threadIdx.x;                 // 256
    const int b   = blockIdx.x;

    int partial = 0;
    for (int i = tid; i < b; i += 256) partial += g_bsum[i];
#pragma unroll
    for (int off = 16; off > 0; off >>= 1)
        partial += __shfl_xor_sync(0xffffffffu, partial, off);
    if ((tid & 31) == 0) wsum[tid >> 5] = partial;
    __syncthreads();
    int add = 0;
#pragma unroll
    for (int k = 0; k < 8; k++) add += wsum[k];

    const int base = b * 1024 + tid * 4;
#pragma unroll
    for (int j = 0; j < 4; j++) {
        int i = base + j;
        if (i < RRNN) {
            int o = g_off[i] + add;
            g_off[i] = o;
            g_cur[i] = o;
        }
    }
}

// ---------------------------------------------------------------------------
// fill_w (after GEMM): CSR fill + per-edge weight w = exp(leakyrelu(el+er))
// ---------------------------------------------------------------------------
__global__ void fill_w_kernel(const int* __restrict__ src, const int* __restrict__ dst)
{
    int i = blockIdx.x * blockDim.x + threadIdx.x;
    if (i >= RR * EE) return;
    int r   = i / EE;
    int s   = src[i];
    int idx = r * NN + dst[i];
    int pos = atomicAdd(g_cur + idx, 1);
    float e = g_el[r * NN + s] + g_er[idx];
    e = e >= 0.f ? e : 0.2f * e;
    g_csrc[pos] = s;
    g_wcsr[pos] = __expf(e);
}

// ---------------------------------------------------------------------------
// Fused softmax + aggregation: one warp per dst node, loops all relations.
// phase1: sequential wcsr sum (no random loads, no exp). phase2: pure gather
// with precomputed weights, 4-edge unrolled. Coalesced out write, bias folded.
// ---------------------------------------------------------------------------
__global__ void __launch_bounds__(256) pass_agg_kernel(
    const float* __restrict__ bias, float* __restrict__ out)
{
    const int d    = (blockIdx.x * blockDim.x + threadIdx.x) >> 5;
    const int lane = threadIdx.x & 31;
    if (d >= NN) return;
    const int c0 = lane * 4;

    float4 acc;
    acc.x = (__ldg(bias + c0)     + __ldg(bias + DD + c0)     + __ldg(bias + 2 * DD + c0))     * (1.f / 3.f);
    acc.y = (__ldg(bias + c0 + 1) + __ldg(bias + DD + c0 + 1) + __ldg(bias + 2 * DD + c0 + 1)) * (1.f / 3.f);
    acc.z = (__ldg(bias + c0 + 2) + __ldg(bias + DD + c0 + 2) + __ldg(bias + 2 * DD + c0 + 2)) * (1.f / 3.f);
    acc.w = (__ldg(bias + c0 + 3) + __ldg(bias + DD + c0 + 3) + __ldg(bias + 2 * DD + c0 + 3)) * (1.f / 3.f);

#pragma unroll
    for (int r = 0; r < RR; r++) {
        const int idx = r * NN + d;
        const int beg = g_off[idx];
        const int end = g_cur[idx];
        if (beg == end) continue;

        // phase 1: sum of precomputed weights (sequential reads)
        float s = 0.f;
        for (int j = beg + lane; j < end; j += 32) s += g_wcsr[j];
#pragma unroll
        for (int off = 16; off > 0; off >>= 1)
            s += __shfl_xor_sync(0xffffffffu, s, off);
        const float inv = 1.0f / (s * 3.0f);

        // phase 2: weighted gather of fp16 rows, 4-edge unrolled for MLP
        const __half* featr = g_feat + (size_t)r * NN * DD;
        int j = beg;
        for (; j + 3 < end; j += 4) {
            int   s0 = g_csrc[j],     s1 = g_csrc[j + 1],
                  s2 = g_csrc[j + 2], s3 = g_csrc[j + 3];
            float w0 = g_wcsr[j]     * inv, w1 = g_wcsr[j + 1] * inv,
                  w2 = g_wcsr[j + 2] * inv, w3 = g_wcsr[j + 3] * inv;
            uint2 p0 = *(const uint2*)(featr + (size_t)s0 * DD + c0);
            uint2 p1 = *(const uint2*)(featr + (size_t)s1 * DD + c0);
            uint2 p2 = *(const uint2*)(featr + (size_t)s2 * DD + c0);
            uint2 p3 = *(const uint2*)(featr + (size_t)s3 * DD + c0);
            float2 a01 = __half22float2(*(__half2*)&p0.x), a23 = __half22float2(*(__half2*)&p0.y);
            float2 b01 = __half22float2(*(__half2*)&p1.x), b23 = __half22float2(*(__half2*)&p1.y);
            float2 c01 = __half22float2(*(__half2*)&p2.x), c23 = __half22float2(*(__half2*)&p2.y);
            float2 d01 = __half22float2(*(__half2*)&p3.x), d23 = __half22float2(*(__half2*)&p3.y);
            acc.x += w0 * a01.x + w1 * b01.x + w2 * c01.x + w3 * d01.x;
            acc.y += w0 * a01.y + w1 * b01.y + w2 * c01.y + w3 * d01.y;
            acc.z += w0 * a23.x + w1 * b23.x + w2 * c23.x + w3 * d23.x;
            acc.w += w0 * a23.y + w1 * b23.y + w2 * c23.y + w3 * d23.y;
        }
        for (; j < end; j++) {
            int   sj = g_csrc[j];
            float w  = g_wcsr[j] * inv;
            uint2 p0 = *(const uint2*)(featr + (size_t)sj * DD + c0);
            float2 a01 = __half22float2(*(__half2*)&p0.x);
            float2 a23 = __half22float2(*(__half2*)&p0.y);
            acc.x += w * a01.x; acc.y += w * a01.y;
            acc.z += w * a23.x; acc.w += w * a23.y;
        }
    }
    *(float4*)(out + (size_t)d * DD + c0) = acc;
}

// ---------------------------------------------------------------------------
// Launch
// ---------------------------------------------------------------------------
extern "C" void kernel_launch(void* const* d_in, const int* in_sizes, int n_in,
                              void* d_out, int out_size)
{
    const float* x    = (const float*)d_in[0];
    const int*   src  = (const int*)  d_in[1];
    const int*   dst  = (const int*)  d_in[2];
    const float* W    = (const float*)d_in[3];
    const float* al   = (const float*)d_in[4];
    const float* ar   = (const float*)d_in[5];
    const float* bias = (const float*)d_in[6];
    float* out = (float*)d_out;

    cudaFuncSetAttribute(gemm_feat_kernel, cudaFuncAttributeMaxDynamicSharedMemorySize, SM_TOT);

    // CSR offsets (independent of GEMM)
    zero_cnt_kernel<<<(RRNN + 255) / 256, 256>>>();
    hist_kernel<<<(RR * EE + 255) / 256, 256>>>(dst);
    scan1_kernel<<<NB1, 256>>>();
    scan23_kernel<<<NB1, 256>>>();

    // Projection + attention logits (all relations per CTA)
    gemm_feat_kernel<<<(NN + 127) / 128, 512, SM_TOT>>>(x, W, al, ar);

    // CSR fill + per-edge weights (needs el/er)
    fill_w_kernel<<<(RR * EE + 255) / 256, 256>>>(src, dst);

    // Fused softmax + aggregation + bias + mean
    pass_agg_kernel<<<(NN * 32 + 255) / 256, 256>>>(bias, out);
}

// round 11
// speedup vs baseline: 1.6654x; 1.0270x over previous
#include <cuda_runtime.h>
#include <cuda_bf16.h>
#include <cuda_fp16.h>
#include <mma.h>
#include <math.h>
#include <stdint.h>

using namespace nvcuda;

// Problem constants
#define NN 100000
#define DD 128
#define EE 500000
#define RR 3
#define RRNN (RR * NN)                 // 300000
#define NB1  ((RRNN + 1023) / 1024)    // 293 scan blocks

// ---------------------------------------------------------------------------
// Static device scratch (allocation-free rule)
// ---------------------------------------------------------------------------
__device__ __half g_feat[(size_t)RR * NN * DD];  // 76.8 MB (fp16 gather)
__device__ float  g_el[RRNN];
__device__ float  g_er[RRNN];
__device__ int    g_cnt[RRNN];
__device__ int    g_off[RRNN];
__device__ int    g_cur[RRNN];
__device__ int    g_bsum[NB1];
__device__ int    g_csrc[(size_t)RR * EE];
__device__ float  g_wcsr[(size_t)RR * EE];       // per-edge exp(e), CSR order

union Pack8 { __nv_bfloat16 h[8]; uint4 u; };

// ---------------------------------------------------------------------------
// GEMM: feat[r] = x @ W[r]^T via bf16x3 split wmma (m16n16k16).
// M-tile 64 rows, 256 threads (8 warps: 2x4), 2 CTAs/SM.
// A (hi/lo, full K) loaded once per CTA; per relation load B, k-loop,
// C staged in smem ALIASED OVER B (dead after k-loop), epilogue writes
// feat (fp16) + el/er (fp32).
// smem: A 34816 + B/C 69632 = 104448 B -> 2 CTAs per SM.
// ---------------------------------------------------------------------------
#define MT    64
#define LDT   136
#define LDC   132
#define TBA   (MT * LDT)               // A tile elems (per hi or lo)
#define TBB   (128 * LDT)              // B tile elems
#define SM_A  0
#define SM_B  (2 * TBA * 2)            // 34816
#define SM_TOT (SM_B + 2 * TBB * 2)    // 104448

__device__ __forceinline__ void split8(const float* __restrict__ p, Pack8& hi, Pack8& lo)
{
    float4 v0 = __ldg((const float4*)p);
    float4 v1 = __ldg((const float4*)(p + 4));
    float wv[8] = {v0.x, v0.y, v0.z, v0.w, v1.x, v1.y, v1.z, v1.w};
#pragma unroll
    for (int j = 0; j < 8; j++) {
        __nv_bfloat16 h = __float2bfloat16(wv[j]);
        hi.h[j] = h;
        lo.h[j] = __float2bfloat16(wv[j] - __bfloat162float(h));
    }
}

__global__ void __launch_bounds__(256, 2) gemm_feat_kernel(
    const float* __restrict__ x, const float* __restrict__ W,
    const float* __restrict__ attn_l, const float* __restrict__ attn_r)
{
    extern __shared__ char smraw[];
    __nv_bfloat16* smA_hi = (__nv_bfloat16*)(smraw + SM_A);
    __nv_bfloat16* smA_lo = smA_hi + TBA;
    __nv_bfloat16* smB_hi = (__nv_bfloat16*)(smraw + SM_B);
    __nv_bfloat16* smB_lo = smB_hi + TBB;
    float*         smC    = (float*)(smraw + SM_B);   // aliased over B

    const int tid  = threadIdx.x;
    const int wid  = tid >> 5;
    const int lane = tid & 31;
    const int row0 = blockIdx.x * MT;
    const int wm   = wid >> 2;      // 0..1 : 32-row slab
    const int wn   = wid & 3;       // 0..3 : 32-col slab

    // --- Load A once: x rows fp32 -> bf16 hi/lo, full K=128 ---
#pragma unroll
    for (int t = 0; t < 4; t++) {
        int idx  = tid + t * 256;          // 0..1023 = 64 rows x 16 chunks
        int row  = idx >> 4;
        int k8   = (idx & 15) << 3;
        int grow = row0 + row;
        Pack8 hi, lo;
        if (grow < NN) {
            split8(x + (size_t)grow * DD + k8, hi, lo);
        } else {
            hi.u = make_uint4(0u, 0u, 0u, 0u); lo.u = hi.u;
        }
        *(uint4*)(smA_hi + row * LDT + k8) = hi.u;
        *(uint4*)(smA_lo + row * LDT + k8) = lo.u;
    }
    __syncthreads();

    for (int rel = 0; rel < RR; rel++) {
        // --- Load B: W[rel][n][k] fp32 -> bf16 hi/lo, full K ---
        const float* Wr = W + (size_t)rel * DD * DD;
#pragma unroll
        for (int t = 0; t < 8; t++) {
            int idx = tid + t * 256;       // 0..2047 = 128 rows x 16 chunks
            int n   = idx >> 4;
            int k8  = (idx & 15) << 3;
            Pack8 hi, lo;
            split8(Wr + (size_t)n * DD + k8, hi, lo);
            *(uint4*)(smB_hi + n * LDT + k8) = hi.u;
            *(uint4*)(smB_lo + n * LDT + k8) = lo.u;
        }
        __syncthreads();

        wmma::fragment<wmma::accumulator, 16, 16, 16, float> acc[2][2];
#pragma unroll
        for (int mi = 0; mi < 2; mi++)
#pragma unroll
            for (int ni = 0; ni < 2; ni++) wmma::fill_fragment(acc[mi][ni], 0.0f);

#pragma unroll 2
        for (int kk = 0; kk < DD; kk += 16) {
            wmma::fragment<wmma::matrix_a, 16, 16, 16, __nv_bfloat16, wmma::row_major> ah[2], alx[2];
            wmma::fragment<wmma::matrix_b, 16, 16, 16, __nv_bfloat16, wmma::col_major> bh[2], blx[2];
#pragma unroll
            for (int mi = 0; mi < 2; mi++) {
                wmma::load_matrix_sync(ah[mi],  smA_hi + (wm * 32 + mi * 16) * LDT + kk, LDT);
                wmma::load_matrix_sync(alx[mi], smA_lo + (wm * 32 + mi * 16) * LDT + kk, LDT);
            }
#pragma unroll
            for (int ni = 0; ni < 2; ni++) {
                wmma::load_matrix_sync(bh[ni],  smB_hi + (wn * 32 + ni * 16) * LDT + kk, LDT);
                wmma::load_matrix_sync(blx[ni], smB_lo + (wn * 32 + ni * 16) * LDT + kk, LDT);
            }
#pragma unroll
            for (int mi = 0; mi < 2; mi++)
#pragma unroll
                for (int ni = 0; ni < 2; ni++) {
                    wmma::mma_sync(acc[mi][ni], ah[mi],  bh[ni],  acc[mi][ni]);
                    wmma::mma_sync(acc[mi][ni], alx[mi], bh[ni],  acc[mi][ni]);
                    wmma::mma_sync(acc[mi][ni], ah[mi],  blx[ni], acc[mi][ni]);
                }
        }
        __syncthreads();   // all B reads done before C overwrites the region

        // --- Epilogue: stage C (aliased over B), write feat + el/er ---
#pragma unroll
        for (int mi = 0; mi < 2; mi++)
#pragma unroll
            for (int ni = 0; ni < 2; ni++)
                wmma::store_matrix_sync(smC + (wm * 32 + mi * 16) * LDC + wn * 32 + ni * 16,
                                        acc[mi][ni], LDC, wmma::mem_row_major);
        __syncthreads();

        const float* al = attn_l + rel * DD;
        const float* ar = attn_r + rel * DD;
        const int c0 = lane * 4;
        const float al0 = __ldg(al + c0), al1 = __ldg(al + c0 + 1),
                    al2 = __ldg(al + c0 + 2), al3 = __ldg(al + c0 + 3);
        const float ar0 = __ldg(ar + c0), ar1 = __ldg(ar + c0 + 1),
                    ar2 = __ldg(ar + c0 + 2), ar3 = __ldg(ar + c0 + 3);

#pragma unroll
        for (int rr = 0; rr < 8; rr++) {
            int row  = wid * 8 + rr;
            int grow = row0 + row;
            float4 v = *(const float4*)(smC + row * LDC + c0);
            float el = v.x * al0 + v.y * al1 + v.z * al2 + v.w * al3;
            float er = v.x * ar0 + v.y * ar1 + v.z * ar2 + v.w * ar3;
#pragma unroll
            for (int off = 16; off > 0; off >>= 1) {
                el += __shfl_xor_sync(0xffffffffu, el, off);
                er += __shfl_xor_sync(0xffffffffu, er, off);
            }
            if (grow < NN) {
                __half2 h01 = __float22half2_rn(make_float2(v.x, v.y));
                __half2 h23 = __float22half2_rn(make_float2(v.z, v.w));
                uint2 pk = make_uint2(*(uint32_t*)&h01, *(uint32_t*)&h23);
                *(uint2*)(g_feat + ((size_t)rel * NN + grow) * DD + c0) = pk;
                if (lane == 0) {
                    g_el[rel * NN + grow] = el;
                    g_er[rel * NN + grow] = er;
                }
            }
        }
        __syncthreads();   // C reads done before next relation's B load
    }
}

// ---------------------------------------------------------------------------
// CSR build: zero -> histogram -> scan1 -> scan23(merged)
// ---------------------------------------------------------------------------
__global__ void zero_cnt_kernel()
{
    int i = blockIdx.x * blockDim.x + threadIdx.x;
    if (i < RRNN) g_cnt[i] = 0;
}

__global__ void hist_kernel(const int* __restrict__ dst)
{
    int i = blockIdx.x * blockDim.x + threadIdx.x;
    if (i >= RR * EE) return;
    int r = i / EE;
    atomicAdd(g_cnt + r * NN + dst[i], 1);
}

__global__ void scan1_kernel()
{
    __shared__ int s[256];
    const int tid  = threadIdx.x;
    const int base = blockIdx.x * 1024 + tid * 4;
    int v[4], run = 0;
#pragma unroll
    for (int j = 0; j < 4; j++) {
        v[j] = (base + j < RRNN) ? g_cnt[base + j] : 0;
        run += v[j];
    }
    s[tid] = run;
    __syncthreads();
    int val = run;
    for (int off = 1; off < 256; off <<= 1) {
        int x = (tid >= off) ? s[tid - off] : 0;
        __syncthreads();
        s[tid] = val = val + x;
        __syncthreads();
    }
    int excl = s[tid] - run;
#pragma unroll
    for (int j = 0; j < 4; j++) {
        if (base + j < RRNN) g_off[base + j] = excl;
        excl += v[j];
    }
    if (tid == 255) g_bsum[blockIdx.x] = s[255];
}

// scan23: each block sums bsum prefix itself, then adds + inits cursors
__global__ void scan23_kernel()
{
    __shared__ int wsum[8];
    const int tid = threadIdx.x;                 // 256
    const int b   = blockIdx.x;

    int partial = 0;
    for (int i = tid; i < b; i += 256) partial += g_bsum[i];
#pragma unroll
    for (int off = 16; off > 0; off >>= 1)
        partial += __shfl_xor_sync(0xffffffffu, partial, off);
    if ((tid & 31) == 0) wsum[tid >> 5] = partial;
    __syncthreads();
    int add = 0;
#pragma unroll
    for (int k = 0; k < 8; k++) add += wsum[k];

    const int base = b * 1024 + tid * 4;
#pragma unroll
    for (int j = 0; j < 4; j++) {
        int i = base + j;
        if (i < RRNN) {
            int o = g_off[i] + add;
            g_off[i] = o;
            g_cur[i] = o;
        }
    }
}

// ---------------------------------------------------------------------------
// fill_w (after GEMM): CSR fill + per-edge weight w = exp(leakyrelu(el+er))
// ---------------------------------------------------------------------------
__global__ void fill_w_kernel(const int* __restrict__ src, const int* __restrict__ dst)
{
    int i = blockIdx.x * blockDim.x + threadIdx.x;
    if (i >= RR * EE) return;
    int r   = i / EE;
    int s   = src[i];
    int idx = r * NN + dst[i];
    int pos = atomicAdd(g_cur + idx, 1);
    float e = g_el[r * NN + s] + g_er[idx];
    e = e >= 0.f ? e : 0.2f * e;
    g_csrc[pos] = s;
    g_wcsr[pos] = __expf(e);
}

// ---------------------------------------------------------------------------
// Fused softmax + aggregation: one warp per dst node, loops all relations.
// phase1: sequential wcsr sum. phase2: pure gather with precomputed weights,
// 4-edge unrolled. Coalesced out write, bias folded.
// ---------------------------------------------------------------------------
__global__ void __launch_bounds__(256) pass_agg_kernel(
    const float* __restrict__ bias, float* __restrict__ out)
{
    const int d    = (blockIdx.x * blockDim.x + threadIdx.x) >> 5;
    const int lane = threadIdx.x & 31;
    if (d >= NN) return;
    const int c0 = lane * 4;

    float4 acc;
    acc.x = (__ldg(bias + c0)     + __ldg(bias + DD + c0)     + __ldg(bias + 2 * DD + c0))     * (1.f / 3.f);
    acc.y = (__ldg(bias + c0 + 1) + __ldg(bias + DD + c0 + 1) + __ldg(bias + 2 * DD + c0 + 1)) * (1.f / 3.f);
    acc.z = (__ldg(bias + c0 + 2) + __ldg(bias + DD + c0 + 2) + __ldg(bias + 2 * DD + c0 + 2)) * (1.f / 3.f);
    acc.w = (__ldg(bias + c0 + 3) + __ldg(bias + DD + c0 + 3) + __ldg(bias + 2 * DD + c0 + 3)) * (1.f / 3.f);

#pragma unroll
    for (int r = 0; r < RR; r++) {
        const int idx = r * NN + d;
        const int beg = g_off[idx];
        const int end = g_cur[idx];
        if (beg == end) continue;

        float s = 0.f;
        for (int j = beg + lane; j < end; j += 32) s += g_wcsr[j];
#pragma unroll
        for (int off = 16; off > 0; off >>= 1)
            s += __shfl_xor_sync(0xffffffffu, s, off);
        const float inv = 1.0f / (s * 3.0f);

        const __half* featr = g_feat + (size_t)r * NN * DD;
        int j = beg;
        for (; j + 3 < end; j += 4) {
            int   s0 = g_csrc[j],     s1 = g_csrc[j + 1],
                  s2 = g_csrc[j + 2], s3 = g_csrc[j + 3];
            float w0 = g_wcsr[j]     * inv, w1 = g_wcsr[j + 1] * inv,
                  w2 = g_wcsr[j + 2] * inv, w3 = g_wcsr[j + 3] * inv;
            uint2 p0 = *(const uint2*)(featr + (size_t)s0 * DD + c0);
            uint2 p1 = *(const uint2*)(featr + (size_t)s1 * DD + c0);
            uint2 p2 = *(const uint2*)(featr + (size_t)s2 * DD + c0);
            uint2 p3 = *(const uint2*)(featr + (size_t)s3 * DD + c0);
            float2 a01 = __half22float2(*(__half2*)&p0.x), a23 = __half22float2(*(__half2*)&p0.y);
            float2 b01 = __half22float2(*(__half2*)&p1.x), b23 = __half22float2(*(__half2*)&p1.y);
            float2 c01 = __half22float2(*(__half2*)&p2.x), c23 = __half22float2(*(__half2*)&p2.y);
            float2 d01 = __half22float2(*(__half2*)&p3.x), d23 = __half22float2(*(__half2*)&p3.y);
            acc.x += w0 * a01.x + w1 * b01.x + w2 * c01.x + w3 * d01.x;
            acc.y += w0 * a01.y + w1 * b01.y + w2 * c01.y + w3 * d01.y;
            acc.z += w0 * a23.x + w1 * b23.x + w2 * c23.x + w3 * d23.x;
            acc.w += w0 * a23.y + w1 * b23.y + w2 * c23.y + w3 * d23.y;
        }
        for (; j < end; j++) {
            int   sj = g_csrc[j];
            float w  = g_wcsr[j] * inv;
            uint2 p0 = *(const uint2*)(featr + (size_t)sj * DD + c0);
            float2 a01 = __half22float2(*(__half2*)&p0.x);
            float2 a23 = __half22float2(*(__half2*)&p0.y);
            acc.x += w * a01.x; acc.y += w * a01.y;
            acc.z += w * a23.x; acc.w += w * a23.y;
        }
    }
    *(float4*)(out + (size_t)d * DD + c0) = acc;
}

// ---------------------------------------------------------------------------
// Launch
// ---------------------------------------------------------------------------
extern "C" void kernel_launch(void* const* d_in, const int* in_sizes, int n_in,
                              void* d_out, int out_size)
{
    const float* x    = (const float*)d_in[0];
    const int*   src  = (const int*)  d_in[1];
    const int*   dst  = (const int*)  d_in[2];
    const float* W    = (const float*)d_in[3];
    const float* al   = (const float*)d_in[4];
    const float* ar   = (const float*)d_in[5];
    const float* bias = (const float*)d_in[6];
    float* out = (float*)d_out;

    cudaFuncSetAttribute(gemm_feat_kernel, cudaFuncAttributeMaxDynamicSharedMemorySize, SM_TOT);

    // CSR offsets (independent of GEMM)
    zero_cnt_kernel<<<(RRNN + 255) / 256, 256>>>();
    hist_kernel<<<(RR * EE + 255) / 256, 256>>>(dst);
    scan1_kernel<<<NB1, 256>>>();
    scan23_kernel<<<NB1, 256>>>();

    // Projection + attention logits (all relations per CTA, 2 CTAs/SM)
    gemm_feat_kernel<<<(NN + MT - 1) / MT, 256, SM_TOT>>>(x, W, al, ar);

    // CSR fill + per-edge weights (needs el/er)
    fill_w_kernel<<<(RR * EE + 255) / 256, 256>>>(src, dst);

    // Fused softmax + aggregation + bias + mean
    pass_agg_kernel<<<(NN * 32 + 255) / 256, 256>>>(bias, out);
}

// round 12
// speedup vs baseline: 1.9659x; 1.1805x over previous
#include <cuda_runtime.h>
#include <cuda_fp16.h>
#include <mma.h>
#include <math.h>
#include <stdint.h>

using namespace nvcuda;

// Problem constants
#define NN 100000
#define DD 128
#define EE 500000
#define RR 3
#define RRNN (RR * NN)                 // 300000
#define NB1  ((RRNN + 1023) / 1024)    // 293 scan blocks

// ---------------------------------------------------------------------------
// Static device scratch (allocation-free rule)
// ---------------------------------------------------------------------------
__device__ __half g_feat[(size_t)RR * NN * DD];  // 76.8 MB (fp16 gather)
__device__ float  g_el[RRNN];
__device__ float  g_er[RRNN];
__device__ int    g_cnt[RRNN];
__device__ int    g_off[RRNN];
__device__ int    g_cur[RRNN];
__device__ int    g_bsum[NB1];
__device__ int    g_csrc[(size_t)RR * EE];
__device__ float  g_wcsr[(size_t)RR * EE];       // per-edge exp(e), CSR order

union HPack8 { __half h[8]; uint4 u; };

// ---------------------------------------------------------------------------
// GEMM: feat[r] = x @ W[r]^T via fp16x2 split wmma (m16n16k16).
// x = xh + xl (fp16 pair, ~21-bit exact); W -> fp16 single operand.
// feat = xh*Wh + xl*Wh : 2 MMA terms (vs 3 for bf16x3), 6 frag loads/k-step.
// M-tile 64 rows, 256 threads (8 warps: 2x4), 3 CTAs/SM.
// smem: A hi/lo 34816 + B 34816 (C fp32 stage aliased over B) = 69632 B.
// ---------------------------------------------------------------------------
#define MT    64
#define LDT   136
#define LDC   132
#define TBA   (MT * LDT)               // A tile elems (per hi or lo)
#define TBB   (128 * LDT)              // B tile elems
#define SM_A  0
#define SM_B  (2 * TBA * 2)            // 34816
#define SM_TOT (SM_B + TBB * 2)        // 69632

// x -> fp16 hi/lo split (8 floats)
__device__ __forceinline__ void split8h(const float* __restrict__ p, HPack8& hi, HPack8& lo)
{
    float4 v0 = __ldg((const float4*)p);
    float4 v1 = __ldg((const float4*)(p + 4));
    float wv[8] = {v0.x, v0.y, v0.z, v0.w, v1.x, v1.y, v1.z, v1.w};
#pragma unroll
    for (int j = 0; j < 8; j++) {
        __half h = __float2half_rn(wv[j]);
        hi.h[j] = h;
        lo.h[j] = __float2half_rn(wv[j] - __half2float(h));
    }
}

// W -> fp16 (8 floats)
__device__ __forceinline__ void cvt8h(const float* __restrict__ p, HPack8& hi)
{
    float4 v0 = __ldg((const float4*)p);
    float4 v1 = __ldg((const float4*)(p + 4));
    float wv[8] = {v0.x, v0.y, v0.z, v0.w, v1.x, v1.y, v1.z, v1.w};
#pragma unroll
    for (int j = 0; j < 8; j++) hi.h[j] = __float2half_rn(wv[j]);
}

__global__ void __launch_bounds__(256, 3) gemm_feat_kernel(
    const float* __restrict__ x, const float* __restrict__ W,
    const float* __restrict__ attn_l, const float* __restrict__ attn_r)
{
    extern __shared__ char smraw[];
    __half* smA_hi = (__half*)(smraw + SM_A);
    __half* smA_lo = smA_hi + TBA;
    __half* smB    = (__half*)(smraw + SM_B);
    float*  smC    = (float*)(smraw + SM_B);   // aliased over B

    const int tid  = threadIdx.x;
    const int wid  = tid >> 5;
    const int lane = tid & 31;
    const int row0 = blockIdx.x * MT;
    const int wm   = wid >> 2;      // 0..1 : 32-row slab
    const int wn   = wid & 3;       // 0..3 : 32-col slab

    // --- Load A once: x rows fp32 -> fp16 hi/lo, full K=128 ---
#pragma unroll
    for (int t = 0; t < 4; t++) {
        int idx  = tid + t * 256;          // 0..1023 = 64 rows x 16 chunks
        int row  = idx >> 4;
        int k8   = (idx & 15) << 3;
        int grow = row0 + row;
        HPack8 hi, lo;
        if (grow < NN) {
            split8h(x + (size_t)grow * DD + k8, hi, lo);
        } else {
            hi.u = make_uint4(0u, 0u, 0u, 0u); lo.u = hi.u;
        }
        *(uint4*)(smA_hi + row * LDT + k8) = hi.u;
        *(uint4*)(smA_lo + row * LDT + k8) = lo.u;
    }
    __syncthreads();

    for (int rel = 0; rel < RR; rel++) {
        // --- Load B: W[rel][n][k] fp32 -> fp16, full K ---
        const float* Wr = W + (size_t)rel * DD * DD;
#pragma unroll
        for (int t = 0; t < 8; t++) {
            int idx = tid + t * 256;       // 0..2047 = 128 rows x 16 chunks
            int n   = idx >> 4;
            int k8  = (idx & 15) << 3;
            HPack8 hv;
            cvt8h(Wr + (size_t)n * DD + k8, hv);
            *(uint4*)(smB + n * LDT + k8) = hv.u;
        }
        __syncthreads();

        wmma::fragment<wmma::accumulator, 16, 16, 16, float> acc[2][2];
#pragma unroll
        for (int mi = 0; mi < 2; mi++)
#pragma unroll
            for (int ni = 0; ni < 2; ni++) wmma::fill_fragment(acc[mi][ni], 0.0f);

#pragma unroll 2
        for (int kk = 0; kk < DD; kk += 16) {
            wmma::fragment<wmma::matrix_a, 16, 16, 16, __half, wmma::row_major> ah[2], alx[2];
            wmma::fragment<wmma::matrix_b, 16, 16, 16, __half, wmma::col_major> bh[2];
#pragma unroll
            for (int mi = 0; mi < 2; mi++) {
                wmma::load_matrix_sync(ah[mi],  smA_hi + (wm * 32 + mi * 16) * LDT + kk, LDT);
                wmma::load_matrix_sync(alx[mi], smA_lo + (wm * 32 + mi * 16) * LDT + kk, LDT);
            }
#pragma unroll
            for (int ni = 0; ni < 2; ni++)
                wmma::load_matrix_sync(bh[ni], smB + (wn * 32 + ni * 16) * LDT + kk, LDT);
#pragma unroll
            for (int mi = 0; mi < 2; mi++)
#pragma unroll
                for (int ni = 0; ni < 2; ni++) {
                    wmma::mma_sync(acc[mi][ni], ah[mi],  bh[ni], acc[mi][ni]);
                    wmma::mma_sync(acc[mi][ni], alx[mi], bh[ni], acc[mi][ni]);
                }
        }
        __syncthreads();   // all B reads done before C overwrites the region

        // --- Epilogue: stage C (aliased over B), write feat + el/er ---
#pragma unroll
        for (int mi = 0; mi < 2; mi++)
#pragma unroll
            for (int ni = 0; ni < 2; ni++)
                wmma::store_matrix_sync(smC + (wm * 32 + mi * 16) * LDC + wn * 32 + ni * 16,
                                        acc[mi][ni], LDC, wmma::mem_row_major);
        __syncthreads();

        const float* al = attn_l + rel * DD;
        const float* ar = attn_r + rel * DD;
        const int c0 = lane * 4;
        const float al0 = __ldg(al + c0), al1 = __ldg(al + c0 + 1),
                    al2 = __ldg(al + c0 + 2), al3 = __ldg(al + c0 + 3);
        const float ar0 = __ldg(ar + c0), ar1 = __ldg(ar + c0 + 1),
                    ar2 = __ldg(ar + c0 + 2), ar3 = __ldg(ar + c0 + 3);

#pragma unroll
        for (int rr = 0; rr < 8; rr++) {
            int row  = wid * 8 + rr;
            int grow = row0 + row;
            float4 v = *(const float4*)(smC + row * LDC + c0);
            float el = v.x * al0 + v.y * al1 + v.z * al2 + v.w * al3;
            float er = v.x * ar0 + v.y * ar1 + v.z * ar2 + v.w * ar3;
#pragma unroll
            for (int off = 16; off > 0; off >>= 1) {
                el += __shfl_xor_sync(0xffffffffu, el, off);
                er += __shfl_xor_sync(0xffffffffu, er, off);
            }
            if (grow < NN) {
                __half2 h01 = __float22half2_rn(make_float2(v.x, v.y));
                __half2 h23 = __float22half2_rn(make_float2(v.z, v.w));
                uint2 pk = make_uint2(*(uint32_t*)&h01, *(uint32_t*)&h23);
                *(uint2*)(g_feat + ((size_t)rel * NN + grow) * DD + c0) = pk;
                if (lane == 0) {
                    g_el[rel * NN + grow] = el;
                    g_er[rel * NN + grow] = er;
                }
            }
        }
        __syncthreads();   // C reads done before next relation's B load
    }
}

// ---------------------------------------------------------------------------
// CSR build: zero -> histogram -> scan1 -> scan23(merged)
// ---------------------------------------------------------------------------
__global__ void zero_cnt_kernel()
{
    int i = blockIdx.x * blockDim.x + threadIdx.x;
    if (i < RRNN) g_cnt[i] = 0;
}

__global__ void hist_kernel(const int* __restrict__ dst)
{
    int i = blockIdx.x * blockDim.x + threadIdx.x;
    if (i >= RR * EE) return;
    int r = i / EE;
    atomicAdd(g_cnt + r * NN + dst[i], 1);
}

__global__ void scan1_kernel()
{
    __shared__ int s[256];
    const int tid  = threadIdx.x;
    const int base = blockIdx.x * 1024 + tid * 4;
    int v[4], run = 0;
#pragma unroll
    for (int j = 0; j < 4; j++) {
        v[j] = (base + j < RRNN) ? g_cnt[base + j] : 0;
        run += v[j];
    }
    s[tid] = run;
    __syncthreads();
    int val = run;
    for (int off = 1; off < 256; off <<= 1) {
        int x = (tid >= off) ? s[tid - off] : 0;
        __syncthreads();
        s[tid] = val = val + x;
        __syncthreads();
    }
    int excl = s[tid] - run;
#pragma unroll
    for (int j = 0; j < 4; j++) {
        if (base + j < RRNN) g_off[base + j] = excl;
        excl += v[j];
    }
    if (tid == 255) g_bsum[blockIdx.x] = s[255];
}

// scan23: each block sums bsum prefix itself, then adds + inits cursors
__global__ void scan23_kernel()
{
    __shared__ int wsum[8];
    const int tid = threadIdx.x;                 // 256
    const int b   = blockIdx.x;

    int partial = 0;
    for (int i = tid; i < b; i += 256) partial += g_bsum[i];
#pragma unroll
    for (int off = 16; off > 0; off >>= 1)
        partial += __shfl_xor_sync(0xffffffffu, partial, off);
    if ((tid & 31) == 0) wsum[tid >> 5] = partial;
    __syncthreads();
    int add = 0;
#pragma unroll
    for (int k = 0; k < 8; k++) add += wsum[k];

    const int base = b * 1024 + tid * 4;
#pragma unroll
    for (int j = 0; j < 4; j++) {
        int i = base + j;
        if (i < RRNN) {
            int o = g_off[i] + add;
            g_off[i] = o;
            g_cur[i] = o;
        }
    }
}

// ---------------------------------------------------------------------------
// fill_w (after GEMM): CSR fill + per-edge weight w = exp(leakyrelu(el+er))
// ---------------------------------------------------------------------------
__global__ void fill_w_kernel(const int* __restrict__ src, const int* __restrict__ dst)
{
    int i = blockIdx.x * blockDim.x + threadIdx.x;
    if (i >= RR * EE) return;
    int r   = i / EE;
    int s   = src[i];
    int idx = r * NN + dst[i];
    int pos = atomicAdd(g_cur + idx, 1);
    float e = g_el[r * NN + s] + g_er[idx];
    e = e >= 0.f ? e : 0.2f * e;
    g_csrc[pos] = s;
    g_wcsr[pos] = __expf(e);
}

// ---------------------------------------------------------------------------
// Fused softmax + aggregation: one warp per dst node, loops all relations.
// phase1: sequential wcsr sum. phase2: pure gather with precomputed weights,
// 4-edge unrolled. Coalesced out write, bias folded.
// ---------------------------------------------------------------------------
__global__ void __launch_bounds__(256) pass_agg_kernel(
    const float* __restrict__ bias, float* __restrict__ out)
{
    const int d    = (blockIdx.x * blockDim.x + threadIdx.x) >> 5;
    const int lane = threadIdx.x & 31;
    if (d >= NN) return;
    const int c0 = lane * 4;

    float4 acc;
    acc.x = (__ldg(bias + c0)     + __ldg(bias + DD + c0)     + __ldg(bias + 2 * DD + c0))     * (1.f / 3.f);
    acc.y = (__ldg(bias + c0 + 1) + __ldg(bias + DD + c0 + 1) + __ldg(bias + 2 * DD + c0 + 1)) * (1.f / 3.f);
    acc.z = (__ldg(bias + c0 + 2) + __ldg(bias + DD + c0 + 2) + __ldg(bias + 2 * DD + c0 + 2)) * (1.f / 3.f);
    acc.w = (__ldg(bias + c0 + 3) + __ldg(bias + DD + c0 + 3) + __ldg(bias + 2 * DD + c0 + 3)) * (1.f / 3.f);

#pragma unroll
    for (int r = 0; r < RR; r++) {
        const int idx = r * NN + d;
        const int beg = g_off[idx];
        const int end = g_cur[idx];
        if (beg == end) continue;

        float s = 0.f;
        for (int j = beg + lane; j < end; j += 32) s += g_wcsr[j];
#pragma unroll
        for (int off = 16; off > 0; off >>= 1)
            s += __shfl_xor_sync(0xffffffffu, s, off);
        const float inv = 1.0f / (s * 3.0f);

        const __half* featr = g_feat + (size_t)r * NN * DD;
        int j = beg;
        for (; j + 3 < end; j += 4) {
            int   s0 = g_csrc[j],     s1 = g_csrc[j + 1],
                  s2 = g_csrc[j + 2], s3 = g_csrc[j + 3];
            float w0 = g_wcsr[j]     * inv, w1 = g_wcsr[j + 1] * inv,
                  w2 = g_wcsr[j + 2] * inv, w3 = g_wcsr[j + 3] * inv;
            uint2 p0 = *(const uint2*)(featr + (size_t)s0 * DD + c0);
            uint2 p1 = *(const uint2*)(featr + (size_t)s1 * DD + c0);
            uint2 p2 = *(const uint2*)(featr + (size_t)s2 * DD + c0);
            uint2 p3 = *(const uint2*)(featr + (size_t)s3 * DD + c0);
            float2 a01 = __half22float2(*(__half2*)&p0.x), a23 = __half22float2(*(__half2*)&p0.y);
            float2 b01 = __half22float2(*(__half2*)&p1.x), b23 = __half22float2(*(__half2*)&p1.y);
            float2 c01 = __half22float2(*(__half2*)&p2.x), c23 = __half22float2(*(__half2*)&p2.y);
            float2 d01 = __half22float2(*(__half2*)&p3.x), d23 = __half22float2(*(__half2*)&p3.y);
            acc.x += w0 * a01.x + w1 * b01.x + w2 * c01.x + w3 * d01.x;
            acc.y += w0 * a01.y + w1 * b01.y + w2 * c01.y + w3 * d01.y;
            acc.z += w0 * a23.x + w1 * b23.x + w2 * c23.x + w3 * d23.x;
            acc.w += w0 * a23.y + w1 * b23.y + w2 * c23.y + w3 * d23.y;
        }
        for (; j < end; j++) {
            int   sj = g_csrc[j];
            float w  = g_wcsr[j] * inv;
            uint2 p0 = *(const uint2*)(featr + (size_t)sj * DD + c0);
            float2 a01 = __half22float2(*(__half2*)&p0.x);
            float2 a23 = __half22float2(*(__half2*)&p0.y);
            acc.x += w * a01.x; acc.y += w * a01.y;
            acc.z += w * a23.x; acc.w += w * a23.y;
        }
    }
    *(float4*)(out + (size_t)d * DD + c0) = acc;
}

// ---------------------------------------------------------------------------
// Launch
// ---------------------------------------------------------------------------
extern "C" void kernel_launch(void* const* d_in, const int* in_sizes, int n_in,
                              void* d_out, int out_size)
{
    const float* x    = (const float*)d_in[0];
    const int*   src  = (const int*)  d_in[1];
    const int*   dst  = (const int*)  d_in[2];
    const float* W    = (const float*)d_in[3];
    const float* al   = (const float*)d_in[4];
    const float* ar   = (const float*)d_in[5];
    const float* bias = (const float*)d_in[6];
    float* out = (float*)d_out;

    cudaFuncSetAttribute(gemm_feat_kernel, cudaFuncAttributeMaxDynamicSharedMemorySize, SM_TOT);

    // CSR offsets (independent of GEMM)
    zero_cnt_kernel<<<(RRNN + 255) / 256, 256>>>();
    hist_kernel<<<(RR * EE + 255) / 256, 256>>>(dst);
    scan1_kernel<<<NB1, 256>>>();
    scan23_kernel<<<NB1, 256>>>();

    // Projection + attention logits (fp16x2 split, 3 CTAs/SM)
    gemm_feat_kernel<<<(NN + MT - 1) / MT, 256, SM_TOT>>>(x, W, al, ar);

    // CSR fill + per-edge weights (needs el/er)
    fill_w_kernel<<<(RR * EE + 255) / 256, 256>>>(src, dst);

    // Fused softmax + aggregation + bias + mean
    pass_agg_kernel<<<(NN * 32 + 255) / 256, 256>>>(bias, out);
}

// round 13
// speedup vs baseline: 1.9729x; 1.0036x over previous
#include <cuda_runtime.h>
#include <cuda_fp16.h>
#include <mma.h>
#include <math.h>
#include <stdint.h>

using namespace nvcuda;

// Problem constants
#define NN 100000
#define DD 128
#define EE 500000
#define RR 3
#define RRNN (RR * NN)                 // 300000
#define NB1  ((RRNN + 1023) / 1024)    // 293 scan blocks

// ---------------------------------------------------------------------------
// Static device scratch (allocation-free rule)
// ---------------------------------------------------------------------------
__device__ __half g_x16[(size_t)NN * DD];        // 25.6 MB (gather source, L2-resident)
__device__ __half g_xagg[(size_t)RR * NN * DD];  // 76.8 MB (aggregated x, fp16)
__device__ float  g_vl[RR * DD];                 // W_r^T al_r
__device__ float  g_vr[RR * DD];                 // W_r^T ar_r
__device__ float  g_el[RRNN];
__device__ float  g_er[RRNN];
__device__ int    g_cnt[RRNN];
__device__ int    g_off[RRNN];
__device__ int    g_cur[RRNN];
__device__ int    g_bsum[NB1];
__device__ int    g_csrc[(size_t)RR * EE];
__device__ float  g_wcsr[(size_t)RR * EE];       // per-edge exp(e), CSR order

union HPack8 { __half h[8]; uint4 u; };

// ---------------------------------------------------------------------------
// prep: vl_r = W_r^T al_r, vr_r = W_r^T ar_r  (grid = RR, 128 threads)
// ---------------------------------------------------------------------------
__global__ void prep_vlvr_kernel(const float* __restrict__ W,
                                 const float* __restrict__ al,
                                 const float* __restrict__ ar)
{
    const int r = blockIdx.x;
    const int j = threadIdx.x;            // 0..127 (k index)
    const float* Wr = W + (size_t)r * DD * DD;
    float sl = 0.f, sr = 0.f;
    for (int n = 0; n < DD; n++) {
        float w = __ldg(Wr + (size_t)n * DD + j);
        sl += __ldg(al + r * DD + n) * w;
        sr += __ldg(ar + r * DD + n) * w;
    }
    g_vl[r * DD + j] = sl;
    g_vr[r * DD + j] = sr;
}

// ---------------------------------------------------------------------------
// convert + gemv: one pass over x — write x16 (fp16) and el/er for all rels.
// Warp per row.
// ---------------------------------------------------------------------------
__global__ void __launch_bounds__(256) convert_gemv_kernel(const float* __restrict__ x)
{
    const int row  = (blockIdx.x * blockDim.x + threadIdx.x) >> 5;
    const int lane = threadIdx.x & 31;
    if (row >= NN) return;
    const int c0 = lane * 4;

    float4 v = __ldg((const float4*)(x + (size_t)row * DD + c0));
    __half2 h01 = __float22half2_rn(make_float2(v.x, v.y));
    __half2 h23 = __float22half2_rn(make_float2(v.z, v.w));
    *(uint2*)(g_x16 + (size_t)row * DD + c0) =
        make_uint2(*(uint32_t*)&h01, *(uint32_t*)&h23);

#pragma unroll
    for (int r = 0; r < RR; r++) {
        const float* vl = g_vl + r * DD + c0;
        const float* vr = g_vr + r * DD + c0;
        float el = v.x * vl[0] + v.y * vl[1] + v.z * vl[2] + v.w * vl[3];
        float er = v.x * vr[0] + v.y * vr[1] + v.z * vr[2] + v.w * vr[3];
#pragma unroll
        for (int off = 16; off > 0; off >>= 1) {
            el += __shfl_xor_sync(0xffffffffu, el, off);
            er += __shfl_xor_sync(0xffffffffu, er, off);
        }
        if (lane == 0) {
            g_el[r * NN + row] = el;
            g_er[r * NN + row] = er;
        }
    }
}

// ---------------------------------------------------------------------------
// CSR build: zero -> histogram -> scan1 -> scan23(merged)
// ---------------------------------------------------------------------------
__global__ void zero_cnt_kernel()
{
    int i = blockIdx.x * blockDim.x + threadIdx.x;
    if (i < RRNN) g_cnt[i] = 0;
}

__global__ void hist_kernel(const int* __restrict__ dst)
{
    int i = blockIdx.x * blockDim.x + threadIdx.x;
    if (i >= RR * EE) return;
    int r = i / EE;
    atomicAdd(g_cnt + r * NN + dst[i], 1);
}

__global__ void scan1_kernel()
{
    __shared__ int s[256];
    const int tid  = threadIdx.x;
    const int base = blockIdx.x * 1024 + tid * 4;
    int v[4], run = 0;
#pragma unroll
    for (int j = 0; j < 4; j++) {
        v[j] = (base + j < RRNN) ? g_cnt[base + j] : 0;
        run += v[j];
    }
    s[tid] = run;
    __syncthreads();
    int val = run;
    for (int off = 1; off < 256; off <<= 1) {
        int x = (tid >= off) ? s[tid - off] : 0;
        __syncthreads();
        s[tid] = val = val + x;
        __syncthreads();
    }
    int excl = s[tid] - run;
#pragma unroll
    for (int j = 0; j < 4; j++) {
        if (base + j < RRNN) g_off[base + j] = excl;
        excl += v[j];
    }
    if (tid == 255) g_bsum[blockIdx.x] = s[255];
}

__global__ void scan23_kernel()
{
    __shared__ int wsum[8];
    const int tid = threadIdx.x;                 // 256
    const int b   = blockIdx.x;

    int partial = 0;
    for (int i = tid; i < b; i += 256) partial += g_bsum[i];
#pragma unroll
    for (int off = 16; off > 0; off >>= 1)
        partial += __shfl_xor_sync(0xffffffffu, partial, off);
    if ((tid & 31) == 0) wsum[tid >> 5] = partial;
    __syncthreads();
    int add = 0;
#pragma unroll
    for (int k = 0; k < 8; k++) add += wsum[k];

    const int base = b * 1024 + tid * 4;
#pragma unroll
    for (int j = 0; j < 4; j++) {
        int i = base + j;
        if (i < RRNN) {
            int o = g_off[i] + add;
            g_off[i] = o;
            g_cur[i] = o;
        }
    }
}

// ---------------------------------------------------------------------------
// fill_w: CSR fill + per-edge weight w = exp(leakyrelu(el+er))
// ---------------------------------------------------------------------------
__global__ void fill_w_kernel(const int* __restrict__ src, const int* __restrict__ dst)
{
    int i = blockIdx.x * blockDim.x + threadIdx.x;
    if (i >= RR * EE) return;
    int r   = i / EE;
    int s   = src[i];
    int idx = r * NN + dst[i];
    int pos = atomicAdd(g_cur + idx, 1);
    float e = g_el[r * NN + s] + g_er[idx];
    e = e >= 0.f ? e : 0.2f * e;
    g_csrc[pos] = s;
    g_wcsr[pos] = __expf(e);
}

// ---------------------------------------------------------------------------
// Aggregation in x-space: warp per dst node; per relation gather x16 rows
// with precomputed weights (normalized incl. the 1/3 mean), write xagg fp16.
// ---------------------------------------------------------------------------
__global__ void __launch_bounds__(256) pass_agg_kernel()
{
    const int d    = (blockIdx.x * blockDim.x + threadIdx.x) >> 5;
    const int lane = threadIdx.x & 31;
    if (d >= NN) return;
    const int c0 = lane * 4;

#pragma unroll
    for (int r = 0; r < RR; r++) {
        const int idx = r * NN + d;
        const int beg = g_off[idx];
        const int end = g_cur[idx];
        float4 acc = make_float4(0.f, 0.f, 0.f, 0.f);

        if (beg != end) {
            float s = 0.f;
            for (int j = beg + lane; j < end; j += 32) s += g_wcsr[j];
#pragma unroll
            for (int off = 16; off > 0; off >>= 1)
                s += __shfl_xor_sync(0xffffffffu, s, off);
            const float inv = 1.0f / (s * 3.0f);

            int j = beg;
            for (; j + 3 < end; j += 4) {
                int   s0 = g_csrc[j],     s1 = g_csrc[j + 1],
                      s2 = g_csrc[j + 2], s3 = g_csrc[j + 3];
                float w0 = g_wcsr[j]     * inv, w1 = g_wcsr[j + 1] * inv,
                      w2 = g_wcsr[j + 2] * inv, w3 = g_wcsr[j + 3] * inv;
                uint2 p0 = *(const uint2*)(g_x16 + (size_t)s0 * DD + c0);
                uint2 p1 = *(const uint2*)(g_x16 + (size_t)s1 * DD + c0);
                uint2 p2 = *(const uint2*)(g_x16 + (size_t)s2 * DD + c0);
                uint2 p3 = *(const uint2*)(g_x16 + (size_t)s3 * DD + c0);
                float2 a01 = __half22float2(*(__half2*)&p0.x), a23 = __half22float2(*(__half2*)&p0.y);
                float2 b01 = __half22float2(*(__half2*)&p1.x), b23 = __half22float2(*(__half2*)&p1.y);
                float2 c01 = __half22float2(*(__half2*)&p2.x), c23 = __half22float2(*(__half2*)&p2.y);
                float2 d01 = __half22float2(*(__half2*)&p3.x), d23 = __half22float2(*(__half2*)&p3.y);
                acc.x += w0 * a01.x + w1 * b01.x + w2 * c01.x + w3 * d01.x;
                acc.y += w0 * a01.y + w1 * b01.y + w2 * c01.y + w3 * d01.y;
                acc.z += w0 * a23.x + w1 * b23.x + w2 * c23.x + w3 * d23.x;
                acc.w += w0 * a23.y + w1 * b23.y + w2 * c23.y + w3 * d23.y;
            }
            for (; j < end; j++) {
                int   sj = g_csrc[j];
                float w  = g_wcsr[j] * inv;
                uint2 p0 = *(const uint2*)(g_x16 + (size_t)sj * DD + c0);
                float2 a01 = __half22float2(*(__half2*)&p0.x);
                float2 a23 = __half22float2(*(__half2*)&p0.y);
                acc.x += w * a01.x; acc.y += w * a01.y;
                acc.z += w * a23.x; acc.w += w * a23.y;
            }
        }
        __half2 h01 = __float22half2_rn(make_float2(acc.x, acc.y));
        __half2 h23 = __float22half2_rn(make_float2(acc.z, acc.w));
        *(uint2*)(g_xagg + ((size_t)r * NN + d) * DD + c0) =
            make_uint2(*(uint32_t*)&h01, *(uint32_t*)&h23);
    }
}

// ---------------------------------------------------------------------------
// Final projection: out = sum_r xagg_r @ W_r^T + bias_mean.
// fp16 single-term MMA; acc persists ACROSS relations; one epilogue.
// M-tile 64, 256 threads (8 warps 2x4), 3 CTAs/SM.
// smem: A 17408 + B 34816 (C fp32 stage 33792 aliased over B) = 52224 B.
// ---------------------------------------------------------------------------
#define MT    64
#define LDT   136
#define LDC   132
#define SM_A  0
#define SM_B  (MT * LDT * 2)           // 17408
#define SM_TOT (SM_B + 128 * LDT * 2)  // 52224

__device__ __forceinline__ void cvt8h(const float* __restrict__ p, HPack8& hv)
{
    float4 v0 = __ldg((const float4*)p);
    float4 v1 = __ldg((const float4*)(p + 4));
    float wv[8] = {v0.x, v0.y, v0.z, v0.w, v1.x, v1.y, v1.z, v1.w};
#pragma unroll
    for (int j = 0; j < 8; j++) hv.h[j] = __float2half_rn(wv[j]);
}

__global__ void __launch_bounds__(256, 3) out_gemm_kernel(
    const float* __restrict__ W, const float* __restrict__ bias,
    float* __restrict__ out)
{
    extern __shared__ char smraw[];
    __half* smA = (__half*)(smraw + SM_A);
    __half* smB = (__half*)(smraw + SM_B);
    float*  smC = (float*)(smraw + SM_B);   // aliased over B

    const int tid  = threadIdx.x;
    const int wid  = tid >> 5;
    const int lane = tid & 31;
    const int row0 = blockIdx.x * MT;
    const int wm   = wid >> 2;
    const int wn   = wid & 3;

    wmma::fragment<wmma::accumulator, 16, 16, 16, float> acc[2][2];
#pragma unroll
    for (int mi = 0; mi < 2; mi++)
#pragma unroll
        for (int ni = 0; ni < 2; ni++) wmma::fill_fragment(acc[mi][ni], 0.0f);

    for (int rel = 0; rel < RR; rel++) {
        // A: xagg[rel] fp16 tile (direct copy)
#pragma unroll
        for (int t = 0; t < 4; t++) {
            int idx  = tid + t * 256;        // 64 rows x 16 chunks
            int row  = idx >> 4;
            int k8   = (idx & 15) << 3;
            int grow = row0 + row;
            uint4 v = make_uint4(0u, 0u, 0u, 0u);
            if (grow < NN)
                v = *(const uint4*)(g_xagg + ((size_t)rel * NN + grow) * DD + k8);
            *(uint4*)(smA + row * LDT + k8) = v;
        }
        // B: W[rel] fp32 -> fp16
        const float* Wr = W + (size_t)rel * DD * DD;
#pragma unroll
        for (int t = 0; t < 8; t++) {
            int idx = tid + t * 256;         // 128 rows x 16 chunks
            int n   = idx >> 4;
            int k8  = (idx & 15) << 3;
            HPack8 hv;
            cvt8h(Wr + (size_t)n * DD + k8, hv);
            *(uint4*)(smB + n * LDT + k8) = hv.u;
        }
        __syncthreads();

#pragma unroll 2
        for (int kk = 0; kk < DD; kk += 16) {
            wmma::fragment<wmma::matrix_a, 16, 16, 16, __half, wmma::row_major> af[2];
            wmma::fragment<wmma::matrix_b, 16, 16, 16, __half, wmma::col_major> bf[2];
#pragma unroll
            for (int mi = 0; mi < 2; mi++)
                wmma::load_matrix_sync(af[mi], smA + (wm * 32 + mi * 16) * LDT + kk, LDT);
#pragma unroll
            for (int ni = 0; ni < 2; ni++)
                wmma::load_matrix_sync(bf[ni], smB + (wn * 32 + ni * 16) * LDT + kk, LDT);
#pragma unroll
            for (int mi = 0; mi < 2; mi++)
#pragma unroll
                for (int ni = 0; ni < 2; ni++)
                    wmma::mma_sync(acc[mi][ni], af[mi], bf[ni], acc[mi][ni]);
        }
        __syncthreads();   // A/B reads done before next rel overwrites
    }

    // Epilogue: stage C (aliased over B), add mean bias, write out
#pragma unroll
    for (int mi = 0; mi < 2; mi++)
#pragma unroll
        for (int ni = 0; ni < 2; ni++)
            wmma::store_matrix_sync(smC + (wm * 32 + mi * 16) * LDC + wn * 32 + ni * 16,
                                    acc[mi][ni], LDC, wmma::mem_row_major);
    __syncthreads();

    const int c0 = lane * 4;
    float4 bmean;
    bmean.x = (__ldg(bias + c0)     + __ldg(bias + DD + c0)     + __ldg(bias + 2 * DD + c0))     * (1.f / 3.f);
    bmean.y = (__ldg(bias + c0 + 1) + __ldg(bias + DD + c0 + 1) + __ldg(bias + 2 * DD + c0 + 1)) * (1.f / 3.f);
    bmean.z = (__ldg(bias + c0 + 2) + __ldg(bias + DD + c0 + 2) + __ldg(bias + 2 * DD + c0 + 2)) * (1.f / 3.f);
    bmean.w = (__ldg(bias + c0 + 3) + __ldg(bias + DD + c0 + 3) + __ldg(bias + 2 * DD + c0 + 3)) * (1.f / 3.f);

#pragma unroll
    for (int rr = 0; rr < 8; rr++) {
        int row  = wid * 8 + rr;
        int grow = row0 + row;
        if (grow < NN) {
            float4 v = *(const float4*)(smC + row * LDC + c0);
            v.x += bmean.x; v.y += bmean.y; v.z += bmean.z; v.w += bmean.w;
            *(float4*)(out + (size_t)grow * DD + c0) = v;
        }
    }
}

// ---------------------------------------------------------------------------
// Launch
// ---------------------------------------------------------------------------
extern "C" void kernel_launch(void* const* d_in, const int* in_sizes, int n_in,
                              void* d_out, int out_size)
{
    const float* x    = (const float*)d_in[0];
    const int*   src  = (const int*)  d_in[1];
    const int*   dst  = (const int*)  d_in[2];
    const float* W    = (const float*)d_in[3];
    const float* al   = (const float*)d_in[4];
    const float* ar   = (const float*)d_in[5];
    const float* bias = (const float*)d_in[6];
    float* out = (float*)d_out;

    cudaFuncSetAttribute(out_gemm_kernel, cudaFuncAttributeMaxDynamicSharedMemorySize, SM_TOT);

    // Attention-vector precompute + x conversion + el/er (cheap, unblocks fill_w)
    prep_vlvr_kernel<<<RR, DD>>>(W, al, ar);
    convert_gemv_kernel<<<(NN * 32 + 255) / 256, 256>>>(x);

    // CSR offsets
    zero_cnt_kernel<<<(RRNN + 255) / 256, 256>>>();
    hist_kernel<<<(RR * EE + 255) / 256, 256>>>(dst);
    scan1_kernel<<<NB1, 256>>>();
    scan23_kernel<<<NB1, 256>>>();

    // CSR fill + per-edge weights
    fill_w_kernel<<<(RR * EE + 255) / 256, 256>>>(src, dst);

    // Softmax-weighted aggregation in x-space (L2-resident gather)
    pass_agg_kernel<<<(NN * 32 + 255) / 256, 256>>>();

    // Final projection GEMM + bias + mean
    out_gemm_kernel<<<(NN + MT - 1) / MT, 256, SM_TOT>>>(W, bias, out);
}